// round 9
// baseline (speedup 1.0000x reference)
#include <cuda_runtime.h>

#define S_LEN 4096
#define B_SZ  2
#define DM    512
#define HN    8
#define DH    64
#define NSPLIT 4
#define KPS   (S_LEN / NSPLIT)   // 1024 keys per split
#define KD_ROW (2 * S_LEN)       // 8192 floats per (b,h,d) row of duplicated K

typedef unsigned long long ull;

// ---------------- packed f32x2 helpers (PTX-only on Blackwell) ----------------
__device__ __forceinline__ void ffma2(ull& d, ull a, ull b) {
    asm("fma.rn.f32x2 %0, %1, %2, %0;" : "+l"(d) : "l"(a), "l"(b));
}
__device__ __forceinline__ void fadd2(ull& d, ull a) {
    asm("add.rn.f32x2 %0, %0, %1;" : "+l"(d) : "l"(a));
}
__device__ __forceinline__ ull pack2(float x, float y) {
    ull r; asm("mov.b64 %0, {%1, %2};" : "=l"(r) : "f"(x), "f"(y)); return r;
}
__device__ __forceinline__ void unpack2(ull v, float& x, float& y) {
    asm("mov.b64 {%0, %1}, %2;" : "=f"(x), "=f"(y) : "l"(v));
}
// granule-8 swizzle (Qs / GEMM): col -> swizzled col
__device__ __forceinline__ int swz8(int col, int salt) {
    return ((((col) >> 3) ^ (salt)) << 3) | ((col) & 7);
}

// ---------------- scratch (no cudaMalloc allowed) ----------------
__device__ float g_q[(size_t)B_SZ * S_LEN * DM];
__device__ float g_kd[(size_t)B_SZ * HN * DH * KD_ROW];        // duplicated K, [b,h,d,2s+{0,1}]
__device__ float g_v[(size_t)B_SZ * S_LEN * DM];
__device__ float g_opart[(size_t)NSPLIT * B_SZ * S_LEN * DM];  // unnormalized per-split O
__device__ float g_l[NSPLIT * B_SZ * HN * S_LEN];              // per-split softmax denominators

// merged attention output element (float4): sum_s opart / sum_s l
__device__ __forceinline__ float4 merged_A(int m, int col) {
    int b = m >> 12, q = m & 4095;
    int h = col >> 6, dv = col & 63;
    float4 acc = make_float4(0.f, 0.f, 0.f, 0.f);
    float lsum = 0.f;
    #pragma unroll
    for (int s = 0; s < NSPLIT; s++) {
        const float4 v = *reinterpret_cast<const float4*>(
            &g_opart[((((size_t)s * B_SZ + b) * HN + h) * S_LEN + q) * DH + dv]);
        acc.x += v.x; acc.y += v.y; acc.z += v.z; acc.w += v.w;
        lsum += g_l[((size_t)(s * B_SZ + b) * HN + h) * S_LEN + q];
    }
    float inv = 1.0f / lsum;
    acc.x *= inv; acc.y *= inv; acc.z *= inv; acc.w *= inv;
    return acc;
}

// =====================================================================
// GEMM body: C[m][n] = sum_k A[m][k]*W[n][k] + bias[n]
// MERGE (compile-time): A element = merged attention output.
// dup_k (runtime): epilogue writes transposed duplicated K layout g_kd.
// =====================================================================
template<bool MERGE>
__device__ __forceinline__ void gemm_body(
    const float* __restrict__ A, const float* __restrict__ W,
    const float* __restrict__ bias, float* __restrict__ C, bool dup_k,
    float (*As)[32][128], float (*Ws)[32][128])
{
    const int tid = threadIdx.x;
    const int tx = tid & 15, ty = tid >> 4;
    const int m0 = blockIdx.x * 128;
    const int n0 = blockIdx.y * 128;

    ull acc[4][8];
    #pragma unroll
    for (int i = 0; i < 4; i++)
        #pragma unroll
        for (int j = 0; j < 8; j++) acc[i][j] = 0ull;

    #pragma unroll
    for (int it = 0; it < 4; it++) {
        int e = tid + it * 256;
        int k4 = (e & 7) << 2, r = e >> 3;
        float4 va = MERGE ? merged_A(m0 + r, k4)
                          : *reinterpret_cast<const float4*>(&A[(size_t)(m0 + r) * DM + k4]);
        float4 vw = *reinterpret_cast<const float4*>(&W[(size_t)(n0 + r) * DM + k4]);
        int c0 = swz8(r, k4 >> 2);
        As[0][k4 + 0][c0] = va.x; As[0][k4 + 1][c0] = va.y;
        As[0][k4 + 2][c0] = va.z; As[0][k4 + 3][c0] = va.w;
        Ws[0][k4 + 0][c0] = vw.x; Ws[0][k4 + 1][c0] = vw.y;
        Ws[0][k4 + 2][c0] = vw.z; Ws[0][k4 + 3][c0] = vw.w;
    }
    __syncthreads();

    const int NSLAB = DM / 32;  // 16
    #pragma unroll 1
    for (int s = 0; s < NSLAB; s++) {
        const int buf = s & 1;
        float4 ra[4], rw[4];
        if (s + 1 < NSLAB) {
            const int k0 = (s + 1) * 32;
            #pragma unroll
            for (int it = 0; it < 4; it++) {
                int e = tid + it * 256;
                int k4 = (e & 7) << 2, r = e >> 3;
                ra[it] = MERGE ? merged_A(m0 + r, k0 + k4)
                               : *reinterpret_cast<const float4*>(&A[(size_t)(m0 + r) * DM + k0 + k4]);
                rw[it] = *reinterpret_cast<const float4*>(&W[(size_t)(n0 + r) * DM + k0 + k4]);
            }
        }
        #pragma unroll 4
        for (int k = 0; k < 32; k++) {
            const int salt = k >> 2;
            const float* arow = &As[buf][k][(ty ^ salt) << 3];
            ulonglong2 a0 = *reinterpret_cast<const ulonglong2*>(arow);
            ulonglong2 a1 = *reinterpret_cast<const ulonglong2*>(arow + 4);
            const float* wrow = &Ws[buf][k][(tx ^ salt) << 3];
            float4 w0 = *reinterpret_cast<const float4*>(wrow);
            float4 w1 = *reinterpret_cast<const float4*>(wrow + 4);
            ull wd[8];
            wd[0] = pack2(w0.x, w0.x); wd[1] = pack2(w0.y, w0.y);
            wd[2] = pack2(w0.z, w0.z); wd[3] = pack2(w0.w, w0.w);
            wd[4] = pack2(w1.x, w1.x); wd[5] = pack2(w1.y, w1.y);
            wd[6] = pack2(w1.z, w1.z); wd[7] = pack2(w1.w, w1.w);
            #pragma unroll
            for (int j = 0; j < 8; j++) {
                ffma2(acc[0][j], a0.x, wd[j]);
                ffma2(acc[1][j], a0.y, wd[j]);
                ffma2(acc[2][j], a1.x, wd[j]);
                ffma2(acc[3][j], a1.y, wd[j]);
            }
        }
        if (s + 1 < NSLAB) {
            const int nb = buf ^ 1;
            #pragma unroll
            for (int it = 0; it < 4; it++) {
                int e = tid + it * 256;
                int k4 = (e & 7) << 2, r = e >> 3;
                int c0 = swz8(r, k4 >> 2);
                As[nb][k4 + 0][c0] = ra[it].x; As[nb][k4 + 1][c0] = ra[it].y;
                As[nb][k4 + 2][c0] = ra[it].z; As[nb][k4 + 3][c0] = ra[it].w;
                Ws[nb][k4 + 0][c0] = rw[it].x; Ws[nb][k4 + 1][c0] = rw[it].y;
                Ws[nb][k4 + 2][c0] = rw[it].z; Ws[nb][k4 + 3][c0] = rw[it].w;
            }
        }
        __syncthreads();
    }

    float bb[8];
    #pragma unroll
    for (int j = 0; j < 8; j++) bb[j] = bias[n0 + tx * 8 + j];

    if (!dup_k) {
        #pragma unroll
        for (int mp = 0; mp < 4; mp++) {
            float lo[8], hi[8];
            #pragma unroll
            for (int j = 0; j < 8; j++) unpack2(acc[mp][j], lo[j], hi[j]);
            size_t r0 = (size_t)(m0 + ty * 8 + 2 * mp) * DM + n0 + tx * 8;
            size_t r1 = r0 + DM;
            *reinterpret_cast<float4*>(&C[r0])     = make_float4(lo[0] + bb[0], lo[1] + bb[1], lo[2] + bb[2], lo[3] + bb[3]);
            *reinterpret_cast<float4*>(&C[r0 + 4]) = make_float4(lo[4] + bb[4], lo[5] + bb[5], lo[6] + bb[6], lo[7] + bb[7]);
            *reinterpret_cast<float4*>(&C[r1])     = make_float4(hi[0] + bb[0], hi[1] + bb[1], hi[2] + bb[2], hi[3] + bb[3]);
            *reinterpret_cast<float4*>(&C[r1 + 4]) = make_float4(hi[4] + bb[4], hi[5] + bb[5], hi[6] + bb[6], hi[7] + bb[7]);
        }
    } else {
        // duplicated transposed K: g_kd[((b*8+h)*64 + d) * KD_ROW + 2s + {0,1}]
        #pragma unroll
        for (int mp = 0; mp < 4; mp++) {
            float lo[8], hi[8];
            #pragma unroll
            for (int j = 0; j < 8; j++) unpack2(acc[mp][j], lo[j], hi[j]);
            int m_e = m0 + ty * 8 + 2 * mp;       // even row
            int b = m_e >> 12, ss = m_e & 4095;
            #pragma unroll
            for (int j = 0; j < 8; j++) {
                int n = n0 + tx * 8 + j;
                int h = n >> 6, d = n & 63;
                float ve = lo[j] + bb[j];
                float vo = hi[j] + bb[j];
                size_t base = ((size_t)(b * HN + h) * DH + d) * KD_ROW;
                *reinterpret_cast<float2*>(&C[base + 2 * ss])     = make_float2(ve, ve);
                *reinterpret_cast<float2*>(&C[base + 2 * ss + 2]) = make_float2(vo, vo);
            }
        }
    }
}

// fused QKV projections: z=0 -> Q, z=1 -> K (duplicated layout), z=2 -> V
__global__ void __launch_bounds__(256) qkv_kernel(
    const float* __restrict__ q, const float* __restrict__ k, const float* __restrict__ v,
    const float* __restrict__ Wq, const float* __restrict__ bq,
    const float* __restrict__ Wk, const float* __restrict__ bk,
    const float* __restrict__ Wv, const float* __restrict__ bv,
    float* __restrict__ gq, float* __restrict__ gkd, float* __restrict__ gv)
{
    __shared__ __align__(16) float As[2][32][128];
    __shared__ __align__(16) float Ws[2][32][128];
    const int z = blockIdx.z;
    const float* A    = (z == 0) ? q  : (z == 1) ? k  : v;
    const float* W    = (z == 0) ? Wq : (z == 1) ? Wk : Wv;
    const float* bias = (z == 0) ? bq : (z == 1) ? bk : bv;
    float* C          = (z == 0) ? gq : (z == 1) ? gkd : gv;
    gemm_body<false>(A, W, bias, C, z == 1, As, Ws);
}

// O projection with split-KV merge fused into A staging
__global__ void __launch_bounds__(256) out_kernel(
    const float* __restrict__ Wo, const float* __restrict__ bo, float* __restrict__ C)
{
    __shared__ __align__(16) float As[2][32][128];
    __shared__ __align__(16) float Ws[2][32][128];
    gemm_body<true>(nullptr, Wo, bo, C, false, As, Ws);
}

// =====================================================================
// Flash attention (no-max softmax), split-KV, 128q x 64k tiles, 2 CTA/SM.
// Block 256 = 16(tx) x 16(ty). QK: 8q(4 pairs) x 4 keys {4tx..4tx+3},
// K comes as pre-duplicated (k,k) pairs from g_kd -> ZERO packs in QK.
// PV: 8q x 4 dv {4tx..4tx+3} (R4 pattern, V packed in regs).
// Smem (floats, 28672 = 112 KB):
//   Qs [64][128]  [d][q], granule-8 swizzle salt=(d>>2)&15
//   Ksp[64][128]  [d][dup key pairs], even granules at 0..15, odd at 16..31
//   Vs [64][64]   [kv][dv]
//   Ps [64][128]  [k][q], granule-4 swizzle salt=k>>2
// =====================================================================
#define QS_OFF 0
#define KS_OFF (64 * 128)
#define VS_OFF (KS_OFF + 64 * 128)
#define PS_OFF (VS_OFF + 64 * 64)
#define ATTN_SMEM_FLOATS (PS_OFF + 64 * 128)   // 28672 floats = 114688 B

__global__ void __launch_bounds__(256, 2) attn_kernel(
    const float* __restrict__ Q, const float* __restrict__ Kd,
    const float* __restrict__ V)
{
    extern __shared__ __align__(16) float sm[];
    float* Qs  = sm + QS_OFF;
    float* Ksp = sm + KS_OFF;
    float* Vs  = sm + VS_OFF;
    float* Ps  = sm + PS_OFF;

    const int tid = threadIdx.x;
    const int tx = tid & 15, ty = tid >> 4;
    const int bh = blockIdx.y;
    const int b = bh >> 3, h = bh & 7;
    const int q0 = blockIdx.x * 128;
    const int split = blockIdx.z;
    const int kbase = split * KPS;

    const float* Qb  = Q + (size_t)b * S_LEN * DM + (size_t)h * DH;
    const float* Kdb = Kd + (size_t)(b * HN + h) * DH * KD_ROW;
    const float* Vb  = V + (size_t)b * S_LEN * DM + (size_t)h * DH;

    // ---- stage Q tile (128 q x 64 d) transposed [d][q sw8], pre-scaled ----
    #pragma unroll
    for (int it = 0; it < 8; it++) {
        int e = tid + it * 256;
        int d4 = (e & 15) << 2, qq = e >> 4;
        float4 v = *reinterpret_cast<const float4*>(&Qb[(size_t)(q0 + qq) * DM + d4]);
        int c0 = swz8(qq, (d4 >> 2) & 15);
        Qs[(d4 + 0) * 128 + c0] = v.x * 0.125f;
        Qs[(d4 + 1) * 128 + c0] = v.y * 0.125f;
        Qs[(d4 + 2) * 128 + c0] = v.z * 0.125f;
        Qs[(d4 + 3) * 128 + c0] = v.w * 0.125f;
    }

    ull O2[4][4];
    ull lacc[4];
    #pragma unroll
    for (int i = 0; i < 4; i++) {
        lacc[i] = 0ull;
        #pragma unroll
        for (int j = 0; j < 4; j++) O2[i][j] = 0ull;
    }

    const int ps_g = (2 * ty) ^ tx;   // Ps store granule (salt = kj>>2 = tx)

    #pragma unroll 1
    for (int kt = 0; kt < KPS / 64; kt++) {
        const int kk0 = kbase + kt * 64;
        __syncthreads();   // prior PV done with Ps/Vs, prior QK done with Ksp
        // ---- stage K pairs [d][perm granule] : conflict-free STS.128 ----
        #pragma unroll
        for (int it = 0; it < 8; it++) {
            int e = tid + it * 256;
            int d = e >> 5;                 // 0..63
            int gl = e & 31;                // linear granule 0..31
            float4 kp = *reinterpret_cast<const float4*>(
                &Kdb[(size_t)d * KD_ROW + 2 * kk0 + (gl << 2)]);
            int gp = (gl >> 1) | ((gl & 1) << 4);   // even->0..15, odd->16..31
            *reinterpret_cast<float4*>(&Ksp[d * 128 + (gp << 2)]) = kp;
        }
        // ---- stage V [kv][dv] ----
        #pragma unroll
        for (int it = 0; it < 4; it++) {
            int e = tid + it * 256;
            int d4 = (e & 15) << 2, r = e >> 4;   // r: key 0..63
            float4 vv4 = *reinterpret_cast<const float4*>(&Vb[(size_t)(kk0 + r) * DM + d4]);
            *reinterpret_cast<float4*>(&Vs[r * 64 + d4]) = vv4;
        }
        __syncthreads();

        // ---- S = Qscaled @ K^T : 4 q-pairs x 4 keys (4tx+j), K pairs direct ----
        ull S2[4][4];
        #pragma unroll
        for (int i = 0; i < 4; i++)
            #pragma unroll
            for (int j = 0; j < 4; j++) S2[i][j] = 0ull;

        #pragma unroll 4
        for (int d = 0; d < 64; d++) {
            const int sd = (d >> 2) & 15;
            const float* qrow = &Qs[d * 128 + ((ty ^ sd) << 3)];
            ulonglong2 qa  = *reinterpret_cast<const ulonglong2*>(qrow);
            ulonglong2 qb2 = *reinterpret_cast<const ulonglong2*>(qrow + 4);
            const float* krow = &Ksp[d * 128];
            ulonglong2 k01 = *reinterpret_cast<const ulonglong2*>(krow + (tx << 2));        // keys 4tx,4tx+1
            ulonglong2 k23 = *reinterpret_cast<const ulonglong2*>(krow + 64 + (tx << 2));   // keys 4tx+2,4tx+3
            ffma2(S2[0][0], qa.x,  k01.x); ffma2(S2[0][1], qa.x,  k01.y);
            ffma2(S2[0][2], qa.x,  k23.x); ffma2(S2[0][3], qa.x,  k23.y);
            ffma2(S2[1][0], qa.y,  k01.x); ffma2(S2[1][1], qa.y,  k01.y);
            ffma2(S2[1][2], qa.y,  k23.x); ffma2(S2[1][3], qa.y,  k23.y);
            ffma2(S2[2][0], qb2.x, k01.x); ffma2(S2[2][1], qb2.x, k01.y);
            ffma2(S2[2][2], qb2.x, k23.x); ffma2(S2[2][3], qb2.x, k23.y);
            ffma2(S2[3][0], qb2.y, k01.x); ffma2(S2[3][1], qb2.y, k01.y);
            ffma2(S2[3][2], qb2.y, k23.x); ffma2(S2[3][3], qb2.y, k23.y);
        }

        // ---- P = exp(S); write Ps[kj][q granule ^ tx] ----
        #pragma unroll
        for (int j = 0; j < 4; j++) {
            const int kj = 4 * tx + j;
            ull p[4];
            #pragma unroll
            for (int qp = 0; qp < 4; qp++) {
                float s0, s1;
                unpack2(S2[qp][j], s0, s1);
                p[qp] = pack2(__expf(s0), __expf(s1));
                fadd2(lacc[qp], p[qp]);
            }
            float* prow = &Ps[kj * 128];
            *reinterpret_cast<ulonglong2*>(prow + (ps_g << 2))       = make_ulonglong2(p[0], p[1]);
            *reinterpret_cast<ulonglong2*>(prow + ((ps_g ^ 1) << 2)) = make_ulonglong2(p[2], p[3]);
        }
        __syncthreads();

        // ---- O += P @ V : 4 q-pairs x 4 dv (4tx..4tx+3) ----
        #pragma unroll 4
        for (int kv = 0; kv < 64; kv++) {
            int p0 = (2 * ty) ^ (kv >> 2);
            const float* prow = &Ps[kv * 128];
            ulonglong2 pa = *reinterpret_cast<const ulonglong2*>(prow + (p0 << 2));
            ulonglong2 pb = *reinterpret_cast<const ulonglong2*>(prow + ((p0 ^ 1) << 2));
            float4 vv = *reinterpret_cast<const float4*>(&Vs[kv * 64 + tx * 4]);
            ull vd[4];
            vd[0] = pack2(vv.x, vv.x); vd[1] = pack2(vv.y, vv.y);
            vd[2] = pack2(vv.z, vv.z); vd[3] = pack2(vv.w, vv.w);
            #pragma unroll
            for (int j = 0; j < 4; j++) {
                ffma2(O2[0][j], pa.x, vd[j]);
                ffma2(O2[1][j], pa.y, vd[j]);
                ffma2(O2[2][j], pb.x, vd[j]);
                ffma2(O2[3][j], pb.y, vd[j]);
            }
        }
    }

    // ---- epilogue: reduce l across 16 tx lanes, write unnormalized O + l ----
    float l[8];
    #pragma unroll
    for (int qp = 0; qp < 4; qp++) unpack2(lacc[qp], l[2 * qp], l[2 * qp + 1]);
    #pragma unroll
    for (int i = 0; i < 8; i++) {
        #pragma unroll
        for (int off = 1; off < 16; off <<= 1)
            l[i] += __shfl_xor_sync(0xffffffffu, l[i], off);
    }

    float* Ob = g_opart + ((((size_t)split * B_SZ + b) * HN + h) * S_LEN + q0) * DH;
    #pragma unroll
    for (int qp = 0; qp < 4; qp++) {
        float lo[4], hi[4];
        #pragma unroll
        for (int j = 0; j < 4; j++) unpack2(O2[qp][j], lo[j], hi[j]);
        size_t r0 = (size_t)(ty * 8 + 2 * qp) * DH + tx * 4;
        *reinterpret_cast<float4*>(&Ob[r0])      = make_float4(lo[0], lo[1], lo[2], lo[3]);
        *reinterpret_cast<float4*>(&Ob[r0 + DH]) = make_float4(hi[0], hi[1], hi[2], hi[3]);
    }
    if (tx == 0) {
        float* Lb = g_l + ((size_t)(split * B_SZ + b) * HN + h) * S_LEN + q0 + ty * 8;
        #pragma unroll
        for (int i = 0; i < 8; i++) Lb[i] = l[i];
    }
}

// =====================================================================
extern "C" void kernel_launch(void* const* d_in, const int* in_sizes, int n_in,
                              void* d_out, int out_size)
{
    const float* q  = (const float*)d_in[0];
    const float* k  = (const float*)d_in[1];
    const float* v  = (const float*)d_in[2];
    const float* Wq = (const float*)d_in[3];
    const float* bq = (const float*)d_in[4];
    const float* Wk = (const float*)d_in[5];
    const float* bk = (const float*)d_in[6];
    const float* Wv = (const float*)d_in[7];
    const float* bv = (const float*)d_in[8];
    const float* Wo = (const float*)d_in[9];
    const float* bo = (const float*)d_in[10];
    float* out = (float*)d_out;

    float *gq, *gkd, *gv;
    cudaGetSymbolAddress((void**)&gq, g_q);
    cudaGetSymbolAddress((void**)&gkd, g_kd);
    cudaGetSymbolAddress((void**)&gv, g_v);

    const int ATTN_SMEM = ATTN_SMEM_FLOATS * 4;   // 114688 B -> 2 CTAs/SM
    cudaFuncSetAttribute(attn_kernel, cudaFuncAttributeMaxDynamicSharedMemorySize, ATTN_SMEM);

    // fused Q/K/V projections, K written in duplicated transposed layout
    dim3 qkvgrid(64, 4, 3);
    qkv_kernel<<<qkvgrid, 256>>>(q, k, v, Wq, bq, Wk, bk, Wv, bv, gq, gkd, gv);

    dim3 agrid(S_LEN / 128, B_SZ * HN, NSPLIT);   // (32, 16, 4)
    attn_kernel<<<agrid, 256, ATTN_SMEM>>>(gq, gkd, gv);

    // O projection with split-KV merge fused into A staging
    dim3 ogrid(64, 4);
    out_kernel<<<ogrid, 256>>>(Wo, bo, out);
}

// round 10
// speedup vs baseline: 1.0893x; 1.0893x over previous
#include <cuda_runtime.h>

#define S_LEN 4096
#define B_SZ  2
#define DM    512
#define HN    8
#define DH    64
#define NSPLIT 4
#define KPS   (S_LEN / NSPLIT)   // 1024 keys per split

typedef unsigned long long ull;

// ---------------- packed f32x2 helpers (PTX-only on Blackwell) ----------------
__device__ __forceinline__ void ffma2(ull& d, ull a, ull b) {
    asm("fma.rn.f32x2 %0, %1, %2, %0;" : "+l"(d) : "l"(a), "l"(b));
}
__device__ __forceinline__ void fadd2(ull& d, ull a) {
    asm("add.rn.f32x2 %0, %0, %1;" : "+l"(d) : "l"(a));
}
__device__ __forceinline__ ull pack2(float x, float y) {
    ull r; asm("mov.b64 %0, {%1, %2};" : "=l"(r) : "f"(x), "f"(y)); return r;
}
__device__ __forceinline__ void unpack2(ull v, float& x, float& y) {
    asm("mov.b64 {%0, %1}, %2;" : "=f"(x), "=f"(y) : "l"(v));
}
// granule-8 swizzle (Qs): col -> swizzled col
__device__ __forceinline__ int swz8(int col, int salt) {
    return ((((col) >> 3) ^ (salt)) << 3) | ((col) & 7);
}
// W-granule permutation: rotates bit3 into bit0 so tx and tx+8 land on
// different bank-quads (conflict-free W reads in the GEMM).
__device__ __forceinline__ int wperm(int g) {
    return (((g) & 7) << 1) | (((g) >> 3) & 1);
}

// ---------------- scratch (no cudaMalloc allowed) ----------------
__device__ float g_q[(size_t)B_SZ * S_LEN * DM];
__device__ float g_k[(size_t)B_SZ * S_LEN * DM];
__device__ float g_v[(size_t)B_SZ * S_LEN * DM];
__device__ float g_ctx[(size_t)B_SZ * S_LEN * DM];
__device__ float g_opart[(size_t)NSPLIT * B_SZ * S_LEN * DM];  // unnormalized per-split O
__device__ float g_l[NSPLIT * B_SZ * HN * S_LEN];              // per-split softmax denominators

// =====================================================================
// GEMM: C[m][n] = sum_k A[m][k] * W[n][k] + bias[n]
// M=8192, N=K=512. Tile 256m x 64n, BK=16, 256 threads, 16x4 per thread.
// Issue mix per k: 32 FFMA2 + 4 LDS(A pairs) + 1 LDS(W) + 4 pack = 41 slots.
// A staging: m=tid -> scalar STS rows are 128B/warp (conflict-free).
// W reads: wperm granule permutation -> 2-phase LDS.128.
// =====================================================================
__global__ void __launch_bounds__(256, 2) gemm_bias_kernel(
    const float* __restrict__ A, const float* __restrict__ W,
    const float* __restrict__ bias, float* __restrict__ C)
{
    __shared__ __align__(16) float As[2][16][256];   // [buf][k][m]
    __shared__ __align__(16) float Ws[2][16][64];    // [buf][k][wperm(n/4)*4 + n%4]

    const int tid = threadIdx.x;
    const int tx = tid & 15, ty = tid >> 4;
    const int m0 = blockIdx.x * 256;
    const int n0 = blockIdx.y * 64;

    const int wn = tid & 63;                  // staged W row (n within tile)
    const int wk4 = (tid >> 6) << 2;          // staged W k-offset {0,4,8,12}
    const int wcol = wperm((wn >> 2) & 15) * 4 + (wn & 3);

    ull acc[8][4];
    #pragma unroll
    for (int p = 0; p < 8; p++)
        #pragma unroll
        for (int j = 0; j < 4; j++) acc[p][j] = 0ull;

    // ---- stage slab 0 ----
    {
        const float* arow = &A[(size_t)(m0 + tid) * DM];
        #pragma unroll
        for (int i = 0; i < 4; i++) {
            float4 va = *reinterpret_cast<const float4*>(arow + 4 * i);
            As[0][4 * i + 0][tid] = va.x; As[0][4 * i + 1][tid] = va.y;
            As[0][4 * i + 2][tid] = va.z; As[0][4 * i + 3][tid] = va.w;
        }
        float4 vw = *reinterpret_cast<const float4*>(&W[(size_t)(n0 + wn) * DM + wk4]);
        Ws[0][wk4 + 0][wcol] = vw.x; Ws[0][wk4 + 1][wcol] = vw.y;
        Ws[0][wk4 + 2][wcol] = vw.z; Ws[0][wk4 + 3][wcol] = vw.w;
    }
    __syncthreads();

    const int NSLAB = DM / 16;  // 32
    #pragma unroll 1
    for (int s = 0; s < NSLAB; s++) {
        const int buf = s & 1;
        float4 ra[4], rw;
        if (s + 1 < NSLAB) {
            const int k0 = (s + 1) * 16;
            const float* arow = &A[(size_t)(m0 + tid) * DM + k0];
            #pragma unroll
            for (int i = 0; i < 4; i++)
                ra[i] = *reinterpret_cast<const float4*>(arow + 4 * i);
            rw = *reinterpret_cast<const float4*>(&W[(size_t)(n0 + wn) * DM + k0 + wk4]);
        }
        #pragma unroll 4
        for (int k = 0; k < 16; k++) {
            const float* arow = &As[buf][k][ty * 16];
            ulonglong2 a01 = *reinterpret_cast<const ulonglong2*>(arow);
            ulonglong2 a23 = *reinterpret_cast<const ulonglong2*>(arow + 4);
            ulonglong2 a45 = *reinterpret_cast<const ulonglong2*>(arow + 8);
            ulonglong2 a67 = *reinterpret_cast<const ulonglong2*>(arow + 12);
            float4 w = *reinterpret_cast<const float4*>(&Ws[buf][k][wperm(tx) * 4]);
            ull wd[4];
            wd[0] = pack2(w.x, w.x); wd[1] = pack2(w.y, w.y);
            wd[2] = pack2(w.z, w.z); wd[3] = pack2(w.w, w.w);
            #pragma unroll
            for (int j = 0; j < 4; j++) {
                ffma2(acc[0][j], a01.x, wd[j]);
                ffma2(acc[1][j], a01.y, wd[j]);
                ffma2(acc[2][j], a23.x, wd[j]);
                ffma2(acc[3][j], a23.y, wd[j]);
                ffma2(acc[4][j], a45.x, wd[j]);
                ffma2(acc[5][j], a45.y, wd[j]);
                ffma2(acc[6][j], a67.x, wd[j]);
                ffma2(acc[7][j], a67.y, wd[j]);
            }
        }
        if (s + 1 < NSLAB) {
            const int nb = buf ^ 1;
            #pragma unroll
            for (int i = 0; i < 4; i++) {
                As[nb][4 * i + 0][tid] = ra[i].x; As[nb][4 * i + 1][tid] = ra[i].y;
                As[nb][4 * i + 2][tid] = ra[i].z; As[nb][4 * i + 3][tid] = ra[i].w;
            }
            Ws[nb][wk4 + 0][wcol] = rw.x; Ws[nb][wk4 + 1][wcol] = rw.y;
            Ws[nb][wk4 + 2][wcol] = rw.z; Ws[nb][wk4 + 3][wcol] = rw.w;
        }
        __syncthreads();
    }

    // ---- epilogue: unpack pairs, add bias, store ----
    float4 b4 = *reinterpret_cast<const float4*>(&bias[n0 + tx * 4]);
    #pragma unroll
    for (int p = 0; p < 8; p++) {
        float lo[4], hi[4];
        #pragma unroll
        for (int j = 0; j < 4; j++) unpack2(acc[p][j], lo[j], hi[j]);
        size_t r0 = (size_t)(m0 + ty * 16 + 2 * p) * DM + n0 + tx * 4;
        *reinterpret_cast<float4*>(&C[r0])      = make_float4(lo[0] + b4.x, lo[1] + b4.y, lo[2] + b4.z, lo[3] + b4.w);
        *reinterpret_cast<float4*>(&C[r0 + DM]) = make_float4(hi[0] + b4.x, hi[1] + b4.y, hi[2] + b4.z, hi[3] + b4.w);
    }
}

// =====================================================================
// Flash attention (no-max softmax), split-KV, 128q x 64k tiles, 2 CTA/SM.
// EXACT R4 version (best measured: 1303us, fma 68.2%).
// =====================================================================
#define QS_OFF 0
#define KS_OFF (64 * 128)
#define VS_OFF (KS_OFF + 64 * 64)
#define PS_OFF (VS_OFF + 64 * 64)
#define ATTN_SMEM_FLOATS (PS_OFF + 64 * 128)   // 24576 floats = 96 KB

__global__ void __launch_bounds__(256, 2) attn_kernel(
    const float* __restrict__ Q, const float* __restrict__ K,
    const float* __restrict__ V)
{
    extern __shared__ __align__(16) float sm[];
    float* Qs = sm + QS_OFF;
    float* Ks = sm + KS_OFF;
    float* Vs = sm + VS_OFF;
    float* Ps = sm + PS_OFF;

    const int tid = threadIdx.x;
    const int tx = tid & 15, ty = tid >> 4;
    const int bh = blockIdx.y;
    const int b = bh >> 3, h = bh & 7;
    const int q0 = blockIdx.x * 128;
    const int split = blockIdx.z;
    const int kbase = split * KPS;

    const float* Qb = Q + (size_t)b * S_LEN * DM + (size_t)h * DH;
    const float* Kb = K + (size_t)b * S_LEN * DM + (size_t)h * DH;
    const float* Vb = V + (size_t)b * S_LEN * DM + (size_t)h * DH;

    // stage Q tile (128 q x 64 d) transposed [d][q sw8], pre-scaled by 1/8
    #pragma unroll
    for (int it = 0; it < 8; it++) {
        int e = tid + it * 256;
        int d4 = (e & 15) << 2, qq = e >> 4;
        float4 v = *reinterpret_cast<const float4*>(&Qb[(size_t)(q0 + qq) * DM + d4]);
        int c0 = swz8(qq, (d4 >> 2) & 15);
        Qs[(d4 + 0) * 128 + c0] = v.x * 0.125f;
        Qs[(d4 + 1) * 128 + c0] = v.y * 0.125f;
        Qs[(d4 + 2) * 128 + c0] = v.z * 0.125f;
        Qs[(d4 + 3) * 128 + c0] = v.w * 0.125f;
    }

    ull O2[4][4];
    ull lacc[4];
    #pragma unroll
    for (int i = 0; i < 4; i++) {
        lacc[i] = 0ull;
        #pragma unroll
        for (int j = 0; j < 4; j++) O2[i][j] = 0ull;
    }

    #pragma unroll 1
    for (int kt = 0; kt < KPS / 64; kt++) {
        const int kk0 = kbase + kt * 64;
        __syncthreads();   // prior PV done with Ps/Vs, prior QK done with Ks
        #pragma unroll
        for (int it = 0; it < 4; it++) {
            int e = tid + it * 256;
            int d4 = (e & 15) << 2, r = e >> 4;   // r: key 0..63
            float4 kv4 = *reinterpret_cast<const float4*>(&Kb[(size_t)(kk0 + r) * DM + d4]);
            int c0 = swz8(r, (d4 >> 2) & 7);
            Ks[(d4 + 0) * 64 + c0] = kv4.x;
            Ks[(d4 + 1) * 64 + c0] = kv4.y;
            Ks[(d4 + 2) * 64 + c0] = kv4.z;
            Ks[(d4 + 3) * 64 + c0] = kv4.w;
            float4 vv4 = *reinterpret_cast<const float4*>(&Vb[(size_t)(kk0 + r) * DM + d4]);
            *reinterpret_cast<float4*>(&Vs[r * 64 + d4]) = vv4;
        }
        __syncthreads();

        // ---- S = Qscaled @ K^T : 4 q-pairs x 4 contiguous keys (4tx+j) ----
        ull S2[4][4];
        #pragma unroll
        for (int i = 0; i < 4; i++)
            #pragma unroll
            for (int j = 0; j < 4; j++) S2[i][j] = 0ull;

        #pragma unroll 4
        for (int d = 0; d < 64; d++) {
            const int sd = (d >> 2) & 15;
            const float* qrow = &Qs[d * 128 + ((ty ^ sd) << 3)];
            ulonglong2 qa  = *reinterpret_cast<const ulonglong2*>(qrow);
            ulonglong2 qb2 = *reinterpret_cast<const ulonglong2*>(qrow + 4);
            float4 kv4 = *reinterpret_cast<const float4*>(
                &Ks[d * 64 + ((((tx >> 1) ^ (sd & 7)) << 3) | ((tx & 1) << 2))]);
            ull kd[4];
            kd[0] = pack2(kv4.x, kv4.x); kd[1] = pack2(kv4.y, kv4.y);
            kd[2] = pack2(kv4.z, kv4.z); kd[3] = pack2(kv4.w, kv4.w);
            #pragma unroll
            for (int j = 0; j < 4; j++) {
                ffma2(S2[0][j], qa.x,  kd[j]);
                ffma2(S2[1][j], qa.y,  kd[j]);
                ffma2(S2[2][j], qb2.x, kd[j]);
                ffma2(S2[3][j], qb2.y, kd[j]);
            }
        }

        // ---- P = exp(S); write Ps[k][q-granule ^ (k>>2)] ----
        #pragma unroll
        for (int j = 0; j < 4; j++) {
            const int kj = 4 * tx + j;
            ull p[4];
            #pragma unroll
            for (int qp = 0; qp < 4; qp++) {
                float s0, s1;
                unpack2(S2[qp][j], s0, s1);
                p[qp] = pack2(__expf(s0), __expf(s1));
                fadd2(lacc[qp], p[qp]);
            }
            int p0 = (2 * ty) ^ tx;           // salt = kj>>2 = tx
            float* prow = &Ps[kj * 128];
            *reinterpret_cast<ulonglong2*>(prow + (p0 << 2))       = make_ulonglong2(p[0], p[1]);
            *reinterpret_cast<ulonglong2*>(prow + ((p0 ^ 1) << 2)) = make_ulonglong2(p[2], p[3]);
        }
        __syncthreads();

        // ---- O += P @ V : 4 q-pairs x 4 dv (4tx..4tx+3) ----
        #pragma unroll 4
        for (int kv = 0; kv < 64; kv++) {
            const int sp = kv >> 2;
            int p0 = (2 * ty) ^ sp;
            const float* prow = &Ps[kv * 128];
            ulonglong2 pa = *reinterpret_cast<const ulonglong2*>(prow + (p0 << 2));
            ulonglong2 pb = *reinterpret_cast<const ulonglong2*>(prow + ((p0 ^ 1) << 2));
            float4 vv = *reinterpret_cast<const float4*>(&Vs[kv * 64 + tx * 4]);
            ull vd[4];
            vd[0] = pack2(vv.x, vv.x); vd[1] = pack2(vv.y, vv.y);
            vd[2] = pack2(vv.z, vv.z); vd[3] = pack2(vv.w, vv.w);
            #pragma unroll
            for (int j = 0; j < 4; j++) {
                ffma2(O2[0][j], pa.x, vd[j]);
                ffma2(O2[1][j], pa.y, vd[j]);
                ffma2(O2[2][j], pb.x, vd[j]);
                ffma2(O2[3][j], pb.y, vd[j]);
            }
        }
    }

    // ---- epilogue: reduce l across 16 tx lanes, write unnormalized O + l ----
    float l[8];
    #pragma unroll
    for (int qp = 0; qp < 4; qp++) unpack2(lacc[qp], l[2 * qp], l[2 * qp + 1]);
    #pragma unroll
    for (int i = 0; i < 8; i++) {
        #pragma unroll
        for (int off = 1; off < 16; off <<= 1)
            l[i] += __shfl_xor_sync(0xffffffffu, l[i], off);
    }

    float* Ob = g_opart + ((((size_t)split * B_SZ + b) * HN + h) * S_LEN + q0) * DH;
    #pragma unroll
    for (int qp = 0; qp < 4; qp++) {
        float lo[4], hi[4];
        #pragma unroll
        for (int j = 0; j < 4; j++) unpack2(O2[qp][j], lo[j], hi[j]);
        size_t r0 = (size_t)(ty * 8 + 2 * qp) * DH + tx * 4;
        *reinterpret_cast<float4*>(&Ob[r0])      = make_float4(lo[0], lo[1], lo[2], lo[3]);
        *reinterpret_cast<float4*>(&Ob[r0 + DH]) = make_float4(hi[0], hi[1], hi[2], hi[3]);
    }
    if (tx == 0) {
        float* Lb = g_l + ((size_t)(split * B_SZ + b) * HN + h) * S_LEN + q0 + ty * 8;
        #pragma unroll
        for (int i = 0; i < 8; i++) Lb[i] = l[i];
    }
}

// =====================================================================
// Merge split-KV partials: ctx[b][q][h*64+dv] = sum_s O_s / sum_s l_s
// =====================================================================
__global__ void __launch_bounds__(256) merge_kernel()
{
    int idx = blockIdx.x * 256 + threadIdx.x;
    int dv4 = (idx & 15) << 2;
    int q   = (idx >> 4) & 4095;
    int h   = (idx >> 16) & 7;
    int b   = idx >> 19;

    float sx = 0.f, sy = 0.f, sz = 0.f, sw = 0.f, lsum = 0.f;
    #pragma unroll
    for (int s = 0; s < NSPLIT; s++) {
        size_t ob = ((((size_t)s * B_SZ + b) * HN + h) * S_LEN + q) * DH + dv4;
        float4 v = *reinterpret_cast<const float4*>(&g_opart[ob]);
        sx += v.x; sy += v.y; sz += v.z; sw += v.w;
        lsum += g_l[((size_t)(s * B_SZ + b) * HN + h) * S_LEN + q];
    }
    float inv = 1.0f / lsum;
    size_t co = ((size_t)b * S_LEN + q) * DM + h * DH + dv4;
    *reinterpret_cast<float4*>(&g_ctx[co]) = make_float4(sx * inv, sy * inv, sz * inv, sw * inv);
}

// =====================================================================
extern "C" void kernel_launch(void* const* d_in, const int* in_sizes, int n_in,
                              void* d_out, int out_size)
{
    const float* q  = (const float*)d_in[0];
    const float* k  = (const float*)d_in[1];
    const float* v  = (const float*)d_in[2];
    const float* Wq = (const float*)d_in[3];
    const float* bq = (const float*)d_in[4];
    const float* Wk = (const float*)d_in[5];
    const float* bk = (const float*)d_in[6];
    const float* Wv = (const float*)d_in[7];
    const float* bv = (const float*)d_in[8];
    const float* Wo = (const float*)d_in[9];
    const float* bo = (const float*)d_in[10];
    float* out = (float*)d_out;

    float *gq, *gk, *gv, *gctx;
    cudaGetSymbolAddress((void**)&gq, g_q);
    cudaGetSymbolAddress((void**)&gk, g_k);
    cudaGetSymbolAddress((void**)&gv, g_v);
    cudaGetSymbolAddress((void**)&gctx, g_ctx);

    const int ATTN_SMEM = ATTN_SMEM_FLOATS * 4;   // 98304 B -> 2 CTAs/SM
    cudaFuncSetAttribute(attn_kernel, cudaFuncAttributeMaxDynamicSharedMemorySize, ATTN_SMEM);

    dim3 ggrid(32, 8);   // (8192/256, 512/64)
    gemm_bias_kernel<<<ggrid, 256>>>(q, Wq, bq, gq);
    gemm_bias_kernel<<<ggrid, 256>>>(k, Wk, bk, gk);
    gemm_bias_kernel<<<ggrid, 256>>>(v, Wv, bv, gv);

    dim3 agrid(S_LEN / 128, B_SZ * HN, NSPLIT);   // (32, 16, 4)
    attn_kernel<<<agrid, 256, ATTN_SMEM>>>(gq, gk, gv);

    merge_kernel<<<(B_SZ * HN * S_LEN * (DH / 4)) / 256, 256>>>();   // 8192 blocks

    gemm_bias_kernel<<<ggrid, 256>>>(gctx, Wo, bo, out);
}

// round 12
// speedup vs baseline: 1.2696x; 1.1655x over previous
#include <cuda_runtime.h>
#include <cuda_bf16.h>
#include <cstdint>

#define S_LEN 4096
#define B_SZ  2
#define DM    512
#define HN    8
#define DH    64
#define NSPLIT 4
#define KPS   (S_LEN / NSPLIT)   // 1024 keys per split

typedef unsigned long long ull;

// ---------------- packed f32x2 helpers (PTX-only on Blackwell) ----------------
__device__ __forceinline__ void ffma2(ull& d, ull a, ull b) {
    asm("fma.rn.f32x2 %0, %1, %2, %0;" : "+l"(d) : "l"(a), "l"(b));
}
__device__ __forceinline__ void fadd2(ull& d, ull a) {
    asm("add.rn.f32x2 %0, %0, %1;" : "+l"(d) : "l"(a));
}
__device__ __forceinline__ ull pack2(float x, float y) {
    ull r; asm("mov.b64 %0, {%1, %2};" : "=l"(r) : "f"(x), "f"(y)); return r;
}
__device__ __forceinline__ void unpack2(ull v, float& x, float& y) {
    asm("mov.b64 {%0, %1}, %2;" : "=f"(x), "=f"(y) : "l"(v));
}
// granule-8 swizzle (Qs): col -> swizzled col
__device__ __forceinline__ int swz8(int col, int salt) {
    return ((((col) >> 3) ^ (salt)) << 3) | ((col) & 7);
}

// ---------------- mma.sync helpers (baseline PTX, works under compute_103) ----
#define GSWZ(o) ((o) ^ (((o) >> 3) & 0x70))

__device__ __forceinline__ uint32_t smem_u32(const void* p) {
    uint32_t a;
    asm("{ .reg .u64 t; cvta.to.shared.u64 t, %1; cvt.u32.u64 %0, t; }" : "=r"(a) : "l"(p));
    return a;
}
#define LDM_X4(r, addr)                                                        \
    asm volatile("ldmatrix.sync.aligned.m8n8.x4.shared.b16 {%0,%1,%2,%3}, [%4];" \
        : "=r"((r)[0]), "=r"((r)[1]), "=r"((r)[2]), "=r"((r)[3]) : "r"(addr))

__device__ __forceinline__ void mma16816(float* d, const uint32_t* a, uint32_t b0, uint32_t b1) {
    asm volatile(
        "mma.sync.aligned.m16n8k16.row.col.f32.bf16.bf16.f32 "
        "{%0,%1,%2,%3}, {%4,%5,%6,%7}, {%8,%9}, {%0,%1,%2,%3};"
        : "+f"(d[0]), "+f"(d[1]), "+f"(d[2]), "+f"(d[3])
        : "r"(a[0]), "r"(a[1]), "r"(a[2]), "r"(a[3]), "r"(b0), "r"(b1));
}

// split a float4 into hi/lo bf16 quads (packed as 4x16-bit in a ull)
__device__ __forceinline__ void split4(float4 a, ull& hb, ull& lb) {
    __nv_bfloat16 h0 = __float2bfloat16(a.x), h1 = __float2bfloat16(a.y);
    __nv_bfloat16 h2 = __float2bfloat16(a.z), h3 = __float2bfloat16(a.w);
    __nv_bfloat16 l0 = __float2bfloat16(a.x - __bfloat162float(h0));
    __nv_bfloat16 l1 = __float2bfloat16(a.y - __bfloat162float(h1));
    __nv_bfloat16 l2 = __float2bfloat16(a.z - __bfloat162float(h2));
    __nv_bfloat16 l3 = __float2bfloat16(a.w - __bfloat162float(h3));
    hb = (ull)__bfloat16_as_ushort(h0) | ((ull)__bfloat16_as_ushort(h1) << 16)
       | ((ull)__bfloat16_as_ushort(h2) << 32) | ((ull)__bfloat16_as_ushort(h3) << 48);
    lb = (ull)__bfloat16_as_ushort(l0) | ((ull)__bfloat16_as_ushort(l1) << 16)
       | ((ull)__bfloat16_as_ushort(l2) << 32) | ((ull)__bfloat16_as_ushort(l3) << 48);
}

// ---------------- scratch (no cudaMalloc allowed) ----------------
__device__ float g_q[(size_t)B_SZ * S_LEN * DM];
__device__ float g_k[(size_t)B_SZ * S_LEN * DM];
__device__ float g_v[(size_t)B_SZ * S_LEN * DM];
__device__ float g_ctx[(size_t)B_SZ * S_LEN * DM];
__device__ float g_opart[(size_t)NSPLIT * B_SZ * S_LEN * DM];  // unnormalized per-split O
__device__ float g_l[NSPLIT * B_SZ * HN * S_LEN];              // per-split softmax denominators

// =====================================================================
// Tensor-core GEMM via mma.sync (split-bf16, 3 terms):
//   C[m][n] = sum_k A[m][k]*W[n][k] + bias[n]
// CTA 128m x 128n, 8 warps a 32m x 64n. K-chunks of 64.
// SMEM (64KB dynamic): Ah/Al/Wh/Wl, each bf16[128][64] SW128-swizzled.
// W[n][k] k-contiguous == .col B operand -> ldmatrix without trans.
// =====================================================================
#define TCB_AH 0
#define TCB_AL 16384
#define TCB_WH 32768
#define TCB_WL 49152
#define TC_SMEM 65536

__global__ void __launch_bounds__(256) tc_gemm_kernel(
    const float* __restrict__ A, const float* __restrict__ W,
    const float* __restrict__ bias, float* __restrict__ C)
{
    extern __shared__ __align__(1024) char tcsm[];
    const int tid = threadIdx.x;
    const int lane = tid & 31, wid = tid >> 5;
    const int wr = wid >> 1, wc = wid & 1;        // warp 32m x 64n within 128x128
    const int m0 = blockIdx.x * 128;
    const int n0 = blockIdx.y * 128;
    const uint32_t sb = smem_u32(tcsm);

    float acc[2][8][4];
    #pragma unroll
    for (int mt = 0; mt < 2; mt++)
        #pragma unroll
        for (int nt = 0; nt < 8; nt++)
            #pragma unroll
            for (int i = 0; i < 4; i++) acc[mt][nt][i] = 0.f;

    // per-lane ldmatrix row/col-byte offsets
    const int a_row  = lane & 15;
    const int a_colb = (lane >> 4) << 4;
    const int b_row  = ((lane >> 4) << 3) + (lane & 7);
    const int b_colb = ((lane >> 3) & 1) << 4;

    #pragma unroll 1
    for (int kc = 0; kc < 8; kc++) {
        // ---- stage A/W chunk (128 rows x 64 k), split hi/lo bf16, SW128 ----
        #pragma unroll
        for (int it = 0; it < 8; it++) {
            int e = tid + it * 256;
            int row = e >> 4, kq = e & 15;
            int so = GSWZ(row * 128 + kq * 8);
            ull hb, lb;
            float4 a = *reinterpret_cast<const float4*>(&A[(size_t)(m0 + row) * DM + kc * 64 + kq * 4]);
            split4(a, hb, lb);
            *reinterpret_cast<ull*>(tcsm + TCB_AH + so) = hb;
            *reinterpret_cast<ull*>(tcsm + TCB_AL + so) = lb;
            float4 w = *reinterpret_cast<const float4*>(&W[(size_t)(n0 + row) * DM + kc * 64 + kq * 4]);
            split4(w, hb, lb);
            *reinterpret_cast<ull*>(tcsm + TCB_WH + so) = hb;
            *reinterpret_cast<ull*>(tcsm + TCB_WL + so) = lb;
        }
        __syncthreads();

        #pragma unroll
        for (int k16 = 0; k16 < 4; k16++) {
            const int kb = k16 * 32;
            uint32_t ah[2][4], al[2][4];
            #pragma unroll
            for (int mt = 0; mt < 2; mt++) {
                int ro = (wr * 32 + mt * 16 + a_row) * 128 + kb + a_colb;
                uint32_t ad = sb + GSWZ(ro);
                LDM_X4(ah[mt], ad + TCB_AH);
                LDM_X4(al[mt], ad + TCB_AL);
            }
            #pragma unroll
            for (int p = 0; p < 4; p++) {   // pairs of n8 tiles: n = p*16 .. p*16+15
                int ro = (wc * 64 + p * 16 + b_row) * 128 + kb + b_colb;
                uint32_t bd = sb + GSWZ(ro);
                uint32_t bh[4], bl[4];      // [0,1]=tile n8=2p ; [2,3]=tile n8=2p+1
                LDM_X4(bh, bd + TCB_WH);
                LDM_X4(bl, bd + TCB_WL);
                #pragma unroll
                for (int mt = 0; mt < 2; mt++) {
                    mma16816(acc[mt][2 * p],     ah[mt], bh[0], bh[1]);
                    mma16816(acc[mt][2 * p],     ah[mt], bl[0], bl[1]);
                    mma16816(acc[mt][2 * p],     al[mt], bh[0], bh[1]);
                    mma16816(acc[mt][2 * p + 1], ah[mt], bh[2], bh[3]);
                    mma16816(acc[mt][2 * p + 1], ah[mt], bl[2], bl[3]);
                    mma16816(acc[mt][2 * p + 1], al[mt], bh[2], bh[3]);
                }
            }
        }
        __syncthreads();
    }

    // ---- epilogue: add bias, store fp32 ----
    const int g = lane >> 2, t2 = (lane & 3) << 1;
    #pragma unroll
    for (int nt = 0; nt < 8; nt++) {
        int col = n0 + wc * 64 + nt * 8 + t2;
        float b0 = bias[col], b1 = bias[col + 1];
        #pragma unroll
        for (int mt = 0; mt < 2; mt++) {
            int row = m0 + wr * 32 + mt * 16 + g;
            float2 lo = make_float2(acc[mt][nt][0] + b0, acc[mt][nt][1] + b1);
            float2 hi = make_float2(acc[mt][nt][2] + b0, acc[mt][nt][3] + b1);
            *reinterpret_cast<float2*>(&C[(size_t)row * DM + col])       = lo;
            *reinterpret_cast<float2*>(&C[(size_t)(row + 8) * DM + col]) = hi;
        }
    }
}

// =====================================================================
// Flash attention (no-max softmax), split-KV, 128q x 64k tiles, 2 CTA/SM.
// EXACT best-measured version (1278us, fma 69.2%).
// =====================================================================
#define QS_OFF 0
#define KS_OFF (64 * 128)
#define VS_OFF (KS_OFF + 64 * 64)
#define PS_OFF (VS_OFF + 64 * 64)
#define ATTN_SMEM_FLOATS (PS_OFF + 64 * 128)   // 24576 floats = 96 KB

__global__ void __launch_bounds__(256, 2) attn_kernel(
    const float* __restrict__ Q, const float* __restrict__ K,
    const float* __restrict__ V)
{
    extern __shared__ __align__(16) float sm[];
    float* Qs = sm + QS_OFF;
    float* Ks = sm + KS_OFF;
    float* Vs = sm + VS_OFF;
    float* Ps = sm + PS_OFF;

    const int tid = threadIdx.x;
    const int tx = tid & 15, ty = tid >> 4;
    const int bh = blockIdx.y;
    const int b = bh >> 3, h = bh & 7;
    const int q0 = blockIdx.x * 128;
    const int split = blockIdx.z;
    const int kbase = split * KPS;

    const float* Qb = Q + (size_t)b * S_LEN * DM + (size_t)h * DH;
    const float* Kb = K + (size_t)b * S_LEN * DM + (size_t)h * DH;
    const float* Vb = V + (size_t)b * S_LEN * DM + (size_t)h * DH;

    // stage Q tile (128 q x 64 d) transposed [d][q sw8], pre-scaled by 1/8
    #pragma unroll
    for (int it = 0; it < 8; it++) {
        int e = tid + it * 256;
        int d4 = (e & 15) << 2, qq = e >> 4;
        float4 v = *reinterpret_cast<const float4*>(&Qb[(size_t)(q0 + qq) * DM + d4]);
        int c0 = swz8(qq, (d4 >> 2) & 15);
        Qs[(d4 + 0) * 128 + c0] = v.x * 0.125f;
        Qs[(d4 + 1) * 128 + c0] = v.y * 0.125f;
        Qs[(d4 + 2) * 128 + c0] = v.z * 0.125f;
        Qs[(d4 + 3) * 128 + c0] = v.w * 0.125f;
    }

    ull O2[4][4];
    ull lacc[4];
    #pragma unroll
    for (int i = 0; i < 4; i++) {
        lacc[i] = 0ull;
        #pragma unroll
        for (int j = 0; j < 4; j++) O2[i][j] = 0ull;
    }

    #pragma unroll 1
    for (int kt = 0; kt < KPS / 64; kt++) {
        const int kk0 = kbase + kt * 64;
        __syncthreads();   // prior PV done with Ps/Vs, prior QK done with Ks
        #pragma unroll
        for (int it = 0; it < 4; it++) {
            int e = tid + it * 256;
            int d4 = (e & 15) << 2, r = e >> 4;   // r: key 0..63
            float4 kv4 = *reinterpret_cast<const float4*>(&Kb[(size_t)(kk0 + r) * DM + d4]);
            int c0 = swz8(r, (d4 >> 2) & 7);
            Ks[(d4 + 0) * 64 + c0] = kv4.x;
            Ks[(d4 + 1) * 64 + c0] = kv4.y;
            Ks[(d4 + 2) * 64 + c0] = kv4.z;
            Ks[(d4 + 3) * 64 + c0] = kv4.w;
            float4 vv4 = *reinterpret_cast<const float4*>(&Vb[(size_t)(kk0 + r) * DM + d4]);
            *reinterpret_cast<float4*>(&Vs[r * 64 + d4]) = vv4;
        }
        __syncthreads();

        // ---- S = Qscaled @ K^T : 4 q-pairs x 4 contiguous keys (4tx+j) ----
        ull S2[4][4];
        #pragma unroll
        for (int i = 0; i < 4; i++)
            #pragma unroll
            for (int j = 0; j < 4; j++) S2[i][j] = 0ull;

        #pragma unroll 4
        for (int d = 0; d < 64; d++) {
            const int sd = (d >> 2) & 15;
            const float* qrow = &Qs[d * 128 + ((ty ^ sd) << 3)];
            ulonglong2 qa  = *reinterpret_cast<const ulonglong2*>(qrow);
            ulonglong2 qb2 = *reinterpret_cast<const ulonglong2*>(qrow + 4);
            float4 kv4 = *reinterpret_cast<const float4*>(
                &Ks[d * 64 + ((((tx >> 1) ^ (sd & 7)) << 3) | ((tx & 1) << 2))]);
            ull kd[4];
            kd[0] = pack2(kv4.x, kv4.x); kd[1] = pack2(kv4.y, kv4.y);
            kd[2] = pack2(kv4.z, kv4.z); kd[3] = pack2(kv4.w, kv4.w);
            #pragma unroll
            for (int j = 0; j < 4; j++) {
                ffma2(S2[0][j], qa.x,  kd[j]);
                ffma2(S2[1][j], qa.y,  kd[j]);
                ffma2(S2[2][j], qb2.x, kd[j]);
                ffma2(S2[3][j], qb2.y, kd[j]);
            }
        }

        // ---- P = exp(S); write Ps[k][q-granule ^ (k>>2)] ----
        #pragma unroll
        for (int j = 0; j < 4; j++) {
            const int kj = 4 * tx + j;
            ull p[4];
            #pragma unroll
            for (int qp = 0; qp < 4; qp++) {
                float s0, s1;
                unpack2(S2[qp][j], s0, s1);
                p[qp] = pack2(__expf(s0), __expf(s1));
                fadd2(lacc[qp], p[qp]);
            }
            int p0 = (2 * ty) ^ tx;           // salt = kj>>2 = tx
            float* prow = &Ps[kj * 128];
            *reinterpret_cast<ulonglong2*>(prow + (p0 << 2))       = make_ulonglong2(p[0], p[1]);
            *reinterpret_cast<ulonglong2*>(prow + ((p0 ^ 1) << 2)) = make_ulonglong2(p[2], p[3]);
        }
        __syncthreads();

        // ---- O += P @ V : 4 q-pairs x 4 dv (4tx..4tx+3) ----
        #pragma unroll 4
        for (int kv = 0; kv < 64; kv++) {
            const int sp = kv >> 2;
            int p0 = (2 * ty) ^ sp;
            const float* prow = &Ps[kv * 128];
            ulonglong2 pa = *reinterpret_cast<const ulonglong2*>(prow + (p0 << 2));
            ulonglong2 pb = *reinterpret_cast<const ulonglong2*>(prow + ((p0 ^ 1) << 2));
            float4 vv = *reinterpret_cast<const float4*>(&Vs[kv * 64 + tx * 4]);
            ull vd[4];
            vd[0] = pack2(vv.x, vv.x); vd[1] = pack2(vv.y, vv.y);
            vd[2] = pack2(vv.z, vv.z); vd[3] = pack2(vv.w, vv.w);
            #pragma unroll
            for (int j = 0; j < 4; j++) {
                ffma2(O2[0][j], pa.x, vd[j]);
                ffma2(O2[1][j], pa.y, vd[j]);
                ffma2(O2[2][j], pb.x, vd[j]);
                ffma2(O2[3][j], pb.y, vd[j]);
            }
        }
    }

    // ---- epilogue: reduce l across 16 tx lanes, write unnormalized O + l ----
    float l[8];
    #pragma unroll
    for (int qp = 0; qp < 4; qp++) unpack2(lacc[qp], l[2 * qp], l[2 * qp + 1]);
    #pragma unroll
    for (int i = 0; i < 8; i++) {
        #pragma unroll
        for (int off = 1; off < 16; off <<= 1)
            l[i] += __shfl_xor_sync(0xffffffffu, l[i], off);
    }

    float* Ob = g_opart + ((((size_t)split * B_SZ + b) * HN + h) * S_LEN + q0) * DH;
    #pragma unroll
    for (int qp = 0; qp < 4; qp++) {
        float lo[4], hi[4];
        #pragma unroll
        for (int j = 0; j < 4; j++) unpack2(O2[qp][j], lo[j], hi[j]);
        size_t r0 = (size_t)(ty * 8 + 2 * qp) * DH + tx * 4;
        *reinterpret_cast<float4*>(&Ob[r0])      = make_float4(lo[0], lo[1], lo[2], lo[3]);
        *reinterpret_cast<float4*>(&Ob[r0 + DH]) = make_float4(hi[0], hi[1], hi[2], hi[3]);
    }
    if (tx == 0) {
        float* Lb = g_l + ((size_t)(split * B_SZ + b) * HN + h) * S_LEN + q0 + ty * 8;
        #pragma unroll
        for (int i = 0; i < 8; i++) Lb[i] = l[i];
    }
}

// =====================================================================
// Merge split-KV partials: ctx[b][q][h*64+dv] = sum_s O_s / sum_s l_s
// =====================================================================
__global__ void __launch_bounds__(256) merge_kernel()
{
    int idx = blockIdx.x * 256 + threadIdx.x;
    int dv4 = (idx & 15) << 2;
    int q   = (idx >> 4) & 4095;
    int h   = (idx >> 16) & 7;
    int b   = idx >> 19;

    float sx = 0.f, sy = 0.f, sz = 0.f, sw = 0.f, lsum = 0.f;
    #pragma unroll
    for (int s = 0; s < NSPLIT; s++) {
        size_t ob = ((((size_t)s * B_SZ + b) * HN + h) * S_LEN + q) * DH + dv4;
        float4 v = *reinterpret_cast<const float4*>(&g_opart[ob]);
        sx += v.x; sy += v.y; sz += v.z; sw += v.w;
        lsum += g_l[((size_t)(s * B_SZ + b) * HN + h) * S_LEN + q];
    }
    float inv = 1.0f / lsum;
    size_t co = ((size_t)b * S_LEN + q) * DM + h * DH + dv4;
    *reinterpret_cast<float4*>(&g_ctx[co]) = make_float4(sx * inv, sy * inv, sz * inv, sw * inv);
}

// =====================================================================
extern "C" void kernel_launch(void* const* d_in, const int* in_sizes, int n_in,
                              void* d_out, int out_size)
{
    const float* q  = (const float*)d_in[0];
    const float* k  = (const float*)d_in[1];
    const float* v  = (const float*)d_in[2];
    const float* Wq = (const float*)d_in[3];
    const float* bq = (const float*)d_in[4];
    const float* Wk = (const float*)d_in[5];
    const float* bk = (const float*)d_in[6];
    const float* Wv = (const float*)d_in[7];
    const float* bv = (const float*)d_in[8];
    const float* Wo = (const float*)d_in[9];
    const float* bo = (const float*)d_in[10];
    float* out = (float*)d_out;

    float *gq, *gk, *gv, *gctx;
    cudaGetSymbolAddress((void**)&gq, g_q);
    cudaGetSymbolAddress((void**)&gk, g_k);
    cudaGetSymbolAddress((void**)&gv, g_v);
    cudaGetSymbolAddress((void**)&gctx, g_ctx);

    const int ATTN_SMEM = ATTN_SMEM_FLOATS * 4;   // 98304 B -> 2 CTAs/SM
    cudaFuncSetAttribute(attn_kernel, cudaFuncAttributeMaxDynamicSharedMemorySize, ATTN_SMEM);
    cudaFuncSetAttribute(tc_gemm_kernel, cudaFuncAttributeMaxDynamicSharedMemorySize, TC_SMEM);

    dim3 ggrid(64, 4);   // (8192/128, 512/128)
    tc_gemm_kernel<<<ggrid, 256, TC_SMEM>>>(q, Wq, bq, gq);
    tc_gemm_kernel<<<ggrid, 256, TC_SMEM>>>(k, Wk, bk, gk);
    tc_gemm_kernel<<<ggrid, 256, TC_SMEM>>>(v, Wv, bv, gv);

    dim3 agrid(S_LEN / 128, B_SZ * HN, NSPLIT);   // (32, 16, 4)
    attn_kernel<<<agrid, 256, ATTN_SMEM>>>(gq, gk, gv);

    merge_kernel<<<(B_SZ * HN * S_LEN * (DH / 4)) / 256, 256>>>();   // 8192 blocks

    tc_gemm_kernel<<<ggrid, 256, TC_SMEM>>>(gctx, Wo, bo, out);
}

// round 13
// speedup vs baseline: 2.3562x; 1.8559x over previous
#include <cuda_runtime.h>
#include <cuda_bf16.h>
#include <cstdint>

#define S_LEN 4096
#define B_SZ  2
#define DM    512
#define HN    8
#define DH    64
#define NSPLIT 4
#define KPS   (S_LEN / NSPLIT)   // 1024 keys per split

typedef unsigned long long ull;

// ---------------- mma.sync helpers (baseline PTX, works under compute_103) ----
#define GSWZ(o) ((o) ^ (((o) >> 3) & 0x70))

__device__ __forceinline__ uint32_t smem_u32(const void* p) {
    uint32_t a;
    asm("{ .reg .u64 t; cvta.to.shared.u64 t, %1; cvt.u32.u64 %0, t; }" : "=r"(a) : "l"(p));
    return a;
}
#define LDM_X4(r, addr)                                                        \
    asm volatile("ldmatrix.sync.aligned.m8n8.x4.shared.b16 {%0,%1,%2,%3}, [%4];" \
        : "=r"((r)[0]), "=r"((r)[1]), "=r"((r)[2]), "=r"((r)[3]) : "r"(addr))
#define LDM_X4_T(r, addr)                                                      \
    asm volatile("ldmatrix.sync.aligned.m8n8.x4.trans.shared.b16 {%0,%1,%2,%3}, [%4];" \
        : "=r"((r)[0]), "=r"((r)[1]), "=r"((r)[2]), "=r"((r)[3]) : "r"(addr))

__device__ __forceinline__ void mma16816(float* d, const uint32_t* a, uint32_t b0, uint32_t b1) {
    asm volatile(
        "mma.sync.aligned.m16n8k16.row.col.f32.bf16.bf16.f32 "
        "{%0,%1,%2,%3}, {%4,%5,%6,%7}, {%8,%9}, {%0,%1,%2,%3};"
        : "+f"(d[0]), "+f"(d[1]), "+f"(d[2]), "+f"(d[3])
        : "r"(a[0]), "r"(a[1]), "r"(a[2]), "r"(a[3]), "r"(b0), "r"(b1));
}
// pack {lo, hi} floats to bf16x2 (lo in bits 15:0)
__device__ __forceinline__ uint32_t cvt2(float hi, float lo) {
    uint32_t r; asm("cvt.rn.bf16x2.f32 %0, %1, %2;" : "=r"(r) : "f"(hi), "f"(lo)); return r;
}
// split pair (d0,d1) into hi bf16x2 + residual-lo bf16x2
__device__ __forceinline__ void splitp(float d0, float d1, uint32_t& ph, uint32_t& pl) {
    ph = cvt2(d1, d0);
    float h0 = __uint_as_float(ph << 16);
    float h1 = __uint_as_float(ph & 0xffff0000u);
    pl = cvt2(d1 - h1, d0 - h0);
}
// split a float4 into hi/lo bf16 quads (packed as 4x16-bit in a ull)
__device__ __forceinline__ void split4(float4 a, ull& hb, ull& lb) {
    __nv_bfloat16 h0 = __float2bfloat16(a.x), h1 = __float2bfloat16(a.y);
    __nv_bfloat16 h2 = __float2bfloat16(a.z), h3 = __float2bfloat16(a.w);
    __nv_bfloat16 l0 = __float2bfloat16(a.x - __bfloat162float(h0));
    __nv_bfloat16 l1 = __float2bfloat16(a.y - __bfloat162float(h1));
    __nv_bfloat16 l2 = __float2bfloat16(a.z - __bfloat162float(h2));
    __nv_bfloat16 l3 = __float2bfloat16(a.w - __bfloat162float(h3));
    hb = (ull)__bfloat16_as_ushort(h0) | ((ull)__bfloat16_as_ushort(h1) << 16)
       | ((ull)__bfloat16_as_ushort(h2) << 32) | ((ull)__bfloat16_as_ushort(h3) << 48);
    lb = (ull)__bfloat16_as_ushort(l0) | ((ull)__bfloat16_as_ushort(l1) << 16)
       | ((ull)__bfloat16_as_ushort(l2) << 32) | ((ull)__bfloat16_as_ushort(l3) << 48);
}

// ---------------- scratch (no cudaMalloc allowed) ----------------
__device__ float g_q[(size_t)B_SZ * S_LEN * DM];
__device__ float g_k[(size_t)B_SZ * S_LEN * DM];
__device__ float g_v[(size_t)B_SZ * S_LEN * DM];
__device__ float g_ctx[(size_t)B_SZ * S_LEN * DM];
__device__ float g_opart[(size_t)NSPLIT * B_SZ * S_LEN * DM];  // unnormalized per-split O
__device__ float g_l[NSPLIT * B_SZ * HN * S_LEN];              // per-split softmax denominators

// =====================================================================
// Tensor-core GEMM via mma.sync (split-bf16, 3 terms) — R11-exact.
// =====================================================================
#define TCB_AH 0
#define TCB_AL 16384
#define TCB_WH 32768
#define TCB_WL 49152
#define TC_SMEM 65536

__global__ void __launch_bounds__(256) tc_gemm_kernel(
    const float* __restrict__ A, const float* __restrict__ W,
    const float* __restrict__ bias, float* __restrict__ C)
{
    extern __shared__ __align__(1024) char tcsm[];
    const int tid = threadIdx.x;
    const int lane = tid & 31, wid = tid >> 5;
    const int wr = wid >> 1, wc = wid & 1;
    const int m0 = blockIdx.x * 128;
    const int n0 = blockIdx.y * 128;
    const uint32_t sb = smem_u32(tcsm);

    float acc[2][8][4];
    #pragma unroll
    for (int mt = 0; mt < 2; mt++)
        #pragma unroll
        for (int nt = 0; nt < 8; nt++)
            #pragma unroll
            for (int i = 0; i < 4; i++) acc[mt][nt][i] = 0.f;

    const int a_row  = lane & 15;
    const int a_colb = (lane >> 4) << 4;
    const int b_row  = ((lane >> 4) << 3) + (lane & 7);
    const int b_colb = ((lane >> 3) & 1) << 4;

    #pragma unroll 1
    for (int kc = 0; kc < 8; kc++) {
        #pragma unroll
        for (int it = 0; it < 8; it++) {
            int e = tid + it * 256;
            int row = e >> 4, kq = e & 15;
            int so = GSWZ(row * 128 + kq * 8);
            ull hb, lb;
            float4 a = *reinterpret_cast<const float4*>(&A[(size_t)(m0 + row) * DM + kc * 64 + kq * 4]);
            split4(a, hb, lb);
            *reinterpret_cast<ull*>(tcsm + TCB_AH + so) = hb;
            *reinterpret_cast<ull*>(tcsm + TCB_AL + so) = lb;
            float4 w = *reinterpret_cast<const float4*>(&W[(size_t)(n0 + row) * DM + kc * 64 + kq * 4]);
            split4(w, hb, lb);
            *reinterpret_cast<ull*>(tcsm + TCB_WH + so) = hb;
            *reinterpret_cast<ull*>(tcsm + TCB_WL + so) = lb;
        }
        __syncthreads();

        #pragma unroll
        for (int k16 = 0; k16 < 4; k16++) {
            const int kb = k16 * 32;
            uint32_t ah[2][4], al[2][4];
            #pragma unroll
            for (int mt = 0; mt < 2; mt++) {
                int ro = (wr * 32 + mt * 16 + a_row) * 128 + kb + a_colb;
                uint32_t ad = sb + GSWZ(ro);
                LDM_X4(ah[mt], ad + TCB_AH);
                LDM_X4(al[mt], ad + TCB_AL);
            }
            #pragma unroll
            for (int p = 0; p < 4; p++) {
                int ro = (wc * 64 + p * 16 + b_row) * 128 + kb + b_colb;
                uint32_t bd = sb + GSWZ(ro);
                uint32_t bh[4], bl[4];
                LDM_X4(bh, bd + TCB_WH);
                LDM_X4(bl, bd + TCB_WL);
                #pragma unroll
                for (int mt = 0; mt < 2; mt++) {
                    mma16816(acc[mt][2 * p],     ah[mt], bh[0], bh[1]);
                    mma16816(acc[mt][2 * p],     ah[mt], bl[0], bl[1]);
                    mma16816(acc[mt][2 * p],     al[mt], bh[0], bh[1]);
                    mma16816(acc[mt][2 * p + 1], ah[mt], bh[2], bh[3]);
                    mma16816(acc[mt][2 * p + 1], ah[mt], bl[2], bl[3]);
                    mma16816(acc[mt][2 * p + 1], al[mt], bh[2], bh[3]);
                }
            }
        }
        __syncthreads();
    }

    const int g = lane >> 2, t2 = (lane & 3) << 1;
    #pragma unroll
    for (int nt = 0; nt < 8; nt++) {
        int col = n0 + wc * 64 + nt * 8 + t2;
        float b0 = bias[col], b1 = bias[col + 1];
        #pragma unroll
        for (int mt = 0; mt < 2; mt++) {
            int row = m0 + wr * 32 + mt * 16 + g;
            float2 lo = make_float2(acc[mt][nt][0] + b0, acc[mt][nt][1] + b1);
            float2 hi = make_float2(acc[mt][nt][2] + b0, acc[mt][nt][3] + b1);
            *reinterpret_cast<float2*>(&C[(size_t)row * DM + col])       = lo;
            *reinterpret_cast<float2*>(&C[(size_t)(row + 8) * DM + col]) = hi;
        }
    }
}

// =====================================================================
// Tensor-core flash attention (no-max softmax), split-KV.
// CTA: 128q, chunks of 64 keys. 8 warps, each 16q x 64k.
// QK: 3-term split-bf16; P in regs (accumulator->A-frag identity);
// PV: 3-term, V via ldmatrix.trans. O + l in registers until epilogue.
// SMEM rows padded to 144B (odd granule stride -> conflict-free ldmatrix).
// =====================================================================
#define AQH 0
#define AQL (AQH + 128 * 144)
#define AKH (AQL + 128 * 144)
#define AKL (AKH + 64 * 144)
#define AVH (AKL + 64 * 144)
#define AVL (AVH + 64 * 144)
#define ATTN_SMEM (AVL + 64 * 144)   // 73728 B -> 2 CTAs/SM

__global__ void __launch_bounds__(256, 2) attn_kernel(
    const float* __restrict__ Q, const float* __restrict__ K,
    const float* __restrict__ V)
{
    extern __shared__ __align__(1024) char smc[];
    const int tid = threadIdx.x;
    const int lane = tid & 31, wid = tid >> 5;
    const int bh = blockIdx.y;
    const int b = bh >> 3, h = bh & 7;
    const int q0 = blockIdx.x * 128;
    const int split = blockIdx.z;
    const int kbase = split * KPS;
    const uint32_t sb = smem_u32(smc);

    const float* Qb = Q + (size_t)b * S_LEN * DM + (size_t)h * DH;
    const float* Kb = K + (size_t)b * S_LEN * DM + (size_t)h * DH;
    const float* Vb = V + (size_t)b * S_LEN * DM + (size_t)h * DH;

    // ---- stage Q (scaled by 1/8, split) ----
    #pragma unroll
    for (int it = 0; it < 8; it++) {
        int e = tid + it * 256;
        int d4 = (e & 15) << 2, qq = e >> 4;
        float4 v = *reinterpret_cast<const float4*>(&Qb[(size_t)(q0 + qq) * DM + d4]);
        v.x *= 0.125f; v.y *= 0.125f; v.z *= 0.125f; v.w *= 0.125f;
        ull hb, lb;
        split4(v, hb, lb);
        *reinterpret_cast<ull*>(smc + AQH + qq * 144 + d4 * 2) = hb;
        *reinterpret_cast<ull*>(smc + AQL + qq * 144 + d4 * 2) = lb;
    }

    float oacc[8][4];
    #pragma unroll
    for (int j = 0; j < 8; j++)
        #pragma unroll
        for (int i = 0; i < 4; i++) oacc[j][i] = 0.f;
    float lrow0 = 0.f, lrow1 = 0.f;

    const int a_row  = lane & 15;
    const int a_colb = (lane >> 4) << 4;
    const int kb_row  = ((lane >> 4) << 3) + (lane & 7);   // K (non-trans B)
    const int kb_colb = ((lane >> 3) & 1) << 4;
    const int vb_row  = lane & 15;                          // V (trans B)
    const int vb_colb = (lane >> 4) << 4;

    #pragma unroll 1
    for (int kt = 0; kt < KPS / 64; kt++) {
        const int kk0 = kbase + kt * 64;
        __syncthreads();   // prior PV done reading V; K free
        #pragma unroll
        for (int it = 0; it < 4; it++) {
            int e = tid + it * 256;
            int d4 = (e & 15) << 2, r = e >> 4;
            ull hb, lb;
            float4 kv = *reinterpret_cast<const float4*>(&Kb[(size_t)(kk0 + r) * DM + d4]);
            split4(kv, hb, lb);
            *reinterpret_cast<ull*>(smc + AKH + r * 144 + d4 * 2) = hb;
            *reinterpret_cast<ull*>(smc + AKL + r * 144 + d4 * 2) = lb;
            float4 vv = *reinterpret_cast<const float4*>(&Vb[(size_t)(kk0 + r) * DM + d4]);
            split4(vv, hb, lb);
            *reinterpret_cast<ull*>(smc + AVH + r * 144 + d4 * 2) = hb;
            *reinterpret_cast<ull*>(smc + AVL + r * 144 + d4 * 2) = lb;
        }
        __syncthreads();

        // ---- S = Q @ K^T (3-term split) : 16q x 64k per warp ----
        float sacc[8][4];
        #pragma unroll
        for (int j = 0; j < 8; j++)
            #pragma unroll
            for (int i = 0; i < 4; i++) sacc[j][i] = 0.f;

        #pragma unroll
        for (int k16 = 0; k16 < 4; k16++) {
            uint32_t qa = sb + (wid * 16 + a_row) * 144 + k16 * 32 + a_colb;
            uint32_t ah[4], al[4];
            LDM_X4(ah, qa + AQH);
            LDM_X4(al, qa + AQL);
            #pragma unroll
            for (int p = 0; p < 4; p++) {
                uint32_t ka = sb + (p * 16 + kb_row) * 144 + k16 * 32 + kb_colb;
                uint32_t bh[4], bl[4];
                LDM_X4(bh, ka + AKH);
                LDM_X4(bl, ka + AKL);
                mma16816(sacc[2 * p],     ah, bh[0], bh[1]);
                mma16816(sacc[2 * p],     ah, bl[0], bl[1]);
                mma16816(sacc[2 * p],     al, bh[0], bh[1]);
                mma16816(sacc[2 * p + 1], ah, bh[2], bh[3]);
                mma16816(sacc[2 * p + 1], ah, bl[2], bl[3]);
                mma16816(sacc[2 * p + 1], al, bh[2], bh[3]);
            }
        }

        // ---- P = exp(S) in place; accumulate l ----
        #pragma unroll
        for (int j = 0; j < 8; j++) {
            sacc[j][0] = __expf(sacc[j][0]);
            sacc[j][1] = __expf(sacc[j][1]);
            sacc[j][2] = __expf(sacc[j][2]);
            sacc[j][3] = __expf(sacc[j][3]);
            lrow0 += sacc[j][0] + sacc[j][1];
            lrow1 += sacc[j][2] + sacc[j][3];
        }

        // ---- O += P @ V (P split 2, V split 2; 3 terms) ----
        #pragma unroll
        for (int kq = 0; kq < 4; kq++) {
            const float* t0 = sacc[2 * kq];
            const float* t1 = sacc[2 * kq + 1];
            uint32_t pah[4], pal[4];
            splitp(t0[0], t0[1], pah[0], pal[0]);
            splitp(t0[2], t0[3], pah[1], pal[1]);
            splitp(t1[0], t1[1], pah[2], pal[2]);
            splitp(t1[2], t1[3], pah[3], pal[3]);
            #pragma unroll
            for (int p = 0; p < 4; p++) {
                uint32_t va = sb + (kq * 16 + vb_row) * 144 + p * 32 + vb_colb;
                uint32_t vh[4], vl[4];
                LDM_X4_T(vh, va + AVH);
                LDM_X4_T(vl, va + AVL);
                mma16816(oacc[2 * p],     pah, vh[0], vh[1]);
                mma16816(oacc[2 * p],     pah, vl[0], vl[1]);
                mma16816(oacc[2 * p],     pal, vh[0], vh[1]);
                mma16816(oacc[2 * p + 1], pah, vh[2], vh[3]);
                mma16816(oacc[2 * p + 1], pah, vl[2], vl[3]);
                mma16816(oacc[2 * p + 1], pal, vh[2], vh[3]);
            }
        }
    }

    // ---- epilogue ----
    const int g = lane >> 2, t4 = lane & 3;
    #pragma unroll
    for (int off = 1; off < 4; off <<= 1) {
        lrow0 += __shfl_xor_sync(0xffffffffu, lrow0, off);
        lrow1 += __shfl_xor_sync(0xffffffffu, lrow1, off);
    }

    float* Ob = g_opart + ((((size_t)split * B_SZ + b) * HN + h) * S_LEN + q0) * DH;
    const int r0 = wid * 16 + g, r1 = r0 + 8;
    #pragma unroll
    for (int j = 0; j < 8; j++) {
        int col = j * 8 + t4 * 2;
        *reinterpret_cast<float2*>(&Ob[(size_t)r0 * DH + col]) = make_float2(oacc[j][0], oacc[j][1]);
        *reinterpret_cast<float2*>(&Ob[(size_t)r1 * DH + col]) = make_float2(oacc[j][2], oacc[j][3]);
    }
    if (t4 == 0) {
        float* Lb = g_l + ((size_t)(split * B_SZ + b) * HN + h) * S_LEN + q0;
        Lb[r0] = lrow0;
        Lb[r1] = lrow1;
    }
}

// =====================================================================
// Merge split-KV partials: ctx[b][q][h*64+dv] = sum_s O_s / sum_s l_s
// =====================================================================
__global__ void __launch_bounds__(256) merge_kernel()
{
    int idx = blockIdx.x * 256 + threadIdx.x;
    int dv4 = (idx & 15) << 2;
    int q   = (idx >> 4) & 4095;
    int h   = (idx >> 16) & 7;
    int b   = idx >> 19;

    float sx = 0.f, sy = 0.f, sz = 0.f, sw = 0.f, lsum = 0.f;
    #pragma unroll
    for (int s = 0; s < NSPLIT; s++) {
        size_t ob = ((((size_t)s * B_SZ + b) * HN + h) * S_LEN + q) * DH + dv4;
        float4 v = *reinterpret_cast<const float4*>(&g_opart[ob]);
        sx += v.x; sy += v.y; sz += v.z; sw += v.w;
        lsum += g_l[((size_t)(s * B_SZ + b) * HN + h) * S_LEN + q];
    }
    float inv = 1.0f / lsum;
    size_t co = ((size_t)b * S_LEN + q) * DM + h * DH + dv4;
    *reinterpret_cast<float4*>(&g_ctx[co]) = make_float4(sx * inv, sy * inv, sz * inv, sw * inv);
}

// =====================================================================
extern "C" void kernel_launch(void* const* d_in, const int* in_sizes, int n_in,
                              void* d_out, int out_size)
{
    const float* q  = (const float*)d_in[0];
    const float* k  = (const float*)d_in[1];
    const float* v  = (const float*)d_in[2];
    const float* Wq = (const float*)d_in[3];
    const float* bq = (const float*)d_in[4];
    const float* Wk = (const float*)d_in[5];
    const float* bk = (const float*)d_in[6];
    const float* Wv = (const float*)d_in[7];
    const float* bv = (const float*)d_in[8];
    const float* Wo = (const float*)d_in[9];
    const float* bo = (const float*)d_in[10];
    float* out = (float*)d_out;

    float *gq, *gk, *gv, *gctx;
    cudaGetSymbolAddress((void**)&gq, g_q);
    cudaGetSymbolAddress((void**)&gk, g_k);
    cudaGetSymbolAddress((void**)&gv, g_v);
    cudaGetSymbolAddress((void**)&gctx, g_ctx);

    cudaFuncSetAttribute(attn_kernel, cudaFuncAttributeMaxDynamicSharedMemorySize, ATTN_SMEM);
    cudaFuncSetAttribute(tc_gemm_kernel, cudaFuncAttributeMaxDynamicSharedMemorySize, TC_SMEM);

    dim3 ggrid(64, 4);   // (8192/128, 512/128)
    tc_gemm_kernel<<<ggrid, 256, TC_SMEM>>>(q, Wq, bq, gq);
    tc_gemm_kernel<<<ggrid, 256, TC_SMEM>>>(k, Wk, bk, gk);
    tc_gemm_kernel<<<ggrid, 256, TC_SMEM>>>(v, Wv, bv, gv);

    dim3 agrid(S_LEN / 128, B_SZ * HN, NSPLIT);   // (32, 16, 4)
    attn_kernel<<<agrid, 256, ATTN_SMEM>>>(gq, gk, gv);

    merge_kernel<<<(B_SZ * HN * S_LEN * (DH / 4)) / 256, 256>>>();   // 8192 blocks

    tc_gemm_kernel<<<ggrid, 256, TC_SMEM>>>(gctx, Wo, bo, out);
}

// round 14
// speedup vs baseline: 2.5201x; 1.0696x over previous
#include <cuda_runtime.h>
#include <cuda_bf16.h>
#include <cstdint>

#define S_LEN 4096
#define B_SZ  2
#define DM    512
#define HN    8
#define DH    64
#define NSPLIT 4
#define KPS   (S_LEN / NSPLIT)   // 1024 keys per split

typedef unsigned long long ull;

// ---------------- mma.sync helpers (baseline PTX, works under compute_103) ----
#define GSWZ(o) ((o) ^ (((o) >> 3) & 0x70))

__device__ __forceinline__ uint32_t smem_u32(const void* p) {
    uint32_t a;
    asm("{ .reg .u64 t; cvta.to.shared.u64 t, %1; cvt.u32.u64 %0, t; }" : "=r"(a) : "l"(p));
    return a;
}
#define LDM_X4(r, addr)                                                        \
    asm volatile("ldmatrix.sync.aligned.m8n8.x4.shared.b16 {%0,%1,%2,%3}, [%4];" \
        : "=r"((r)[0]), "=r"((r)[1]), "=r"((r)[2]), "=r"((r)[3]) : "r"(addr))
#define LDM_X4_T(r, addr)                                                      \
    asm volatile("ldmatrix.sync.aligned.m8n8.x4.trans.shared.b16 {%0,%1,%2,%3}, [%4];" \
        : "=r"((r)[0]), "=r"((r)[1]), "=r"((r)[2]), "=r"((r)[3]) : "r"(addr))

__device__ __forceinline__ void mma16816(float* d, const uint32_t* a, uint32_t b0, uint32_t b1) {
    asm volatile(
        "mma.sync.aligned.m16n8k16.row.col.f32.bf16.bf16.f32 "
        "{%0,%1,%2,%3}, {%4,%5,%6,%7}, {%8,%9}, {%0,%1,%2,%3};"
        : "+f"(d[0]), "+f"(d[1]), "+f"(d[2]), "+f"(d[3])
        : "r"(a[0]), "r"(a[1]), "r"(a[2]), "r"(a[3]), "r"(b0), "r"(b1));
}
// pack {lo, hi} floats to bf16x2 (lo in bits 15:0)
__device__ __forceinline__ uint32_t cvt2(float hi, float lo) {
    uint32_t r; asm("cvt.rn.bf16x2.f32 %0, %1, %2;" : "=r"(r) : "f"(hi), "f"(lo)); return r;
}
// split pair (d0,d1) into hi bf16x2 + residual-lo bf16x2
__device__ __forceinline__ void splitp(float d0, float d1, uint32_t& ph, uint32_t& pl) {
    ph = cvt2(d1, d0);
    float h0 = __uint_as_float(ph << 16);
    float h1 = __uint_as_float(ph & 0xffff0000u);
    pl = cvt2(d1 - h1, d0 - h0);
}
// split a float4 into hi/lo bf16 quads (packed as 4x16-bit in a ull)
__device__ __forceinline__ void split4(float4 a, ull& hb, ull& lb) {
    __nv_bfloat16 h0 = __float2bfloat16(a.x), h1 = __float2bfloat16(a.y);
    __nv_bfloat16 h2 = __float2bfloat16(a.z), h3 = __float2bfloat16(a.w);
    __nv_bfloat16 l0 = __float2bfloat16(a.x - __bfloat162float(h0));
    __nv_bfloat16 l1 = __float2bfloat16(a.y - __bfloat162float(h1));
    __nv_bfloat16 l2 = __float2bfloat16(a.z - __bfloat162float(h2));
    __nv_bfloat16 l3 = __float2bfloat16(a.w - __bfloat162float(h3));
    hb = (ull)__bfloat16_as_ushort(h0) | ((ull)__bfloat16_as_ushort(h1) << 16)
       | ((ull)__bfloat16_as_ushort(h2) << 32) | ((ull)__bfloat16_as_ushort(h3) << 48);
    lb = (ull)__bfloat16_as_ushort(l0) | ((ull)__bfloat16_as_ushort(l1) << 16)
       | ((ull)__bfloat16_as_ushort(l2) << 32) | ((ull)__bfloat16_as_ushort(l3) << 48);
}

// ---------------- scratch (no cudaMalloc allowed) ----------------
__device__ __nv_bfloat16 g_qh[(size_t)B_SZ * S_LEN * DM];
__device__ __nv_bfloat16 g_ql[(size_t)B_SZ * S_LEN * DM];
__device__ __nv_bfloat16 g_kh[(size_t)B_SZ * S_LEN * DM];
__device__ __nv_bfloat16 g_kl[(size_t)B_SZ * S_LEN * DM];
__device__ __nv_bfloat16 g_vh[(size_t)B_SZ * S_LEN * DM];
__device__ __nv_bfloat16 g_vl[(size_t)B_SZ * S_LEN * DM];
__device__ float g_ctx[(size_t)B_SZ * S_LEN * DM];
__device__ float g_opart[(size_t)NSPLIT * B_SZ * S_LEN * DM];  // unnormalized per-split O
__device__ float g_l[NSPLIT * B_SZ * HN * S_LEN];              // per-split softmax denominators

// =====================================================================
// Tensor-core GEMM via mma.sync (split-bf16, 3 terms).
// MODE 0: C = fp32 (final output). MODE 1: write split bf16 hi/lo arrays
// (Ch, Cl) with pre-scale applied before the split (Q: 0.125).
// =====================================================================
#define TCB_AH 0
#define TCB_AL 16384
#define TCB_WH 32768
#define TCB_WL 49152
#define TC_SMEM 65536

template<int MODE>
__global__ void __launch_bounds__(256) tc_gemm_kernel(
    const float* __restrict__ A, const float* __restrict__ W,
    const float* __restrict__ bias, float* __restrict__ C,
    __nv_bfloat16* __restrict__ Ch, __nv_bfloat16* __restrict__ Cl, float scale)
{
    extern __shared__ __align__(1024) char tcsm[];
    const int tid = threadIdx.x;
    const int lane = tid & 31, wid = tid >> 5;
    const int wr = wid >> 1, wc = wid & 1;
    const int m0 = blockIdx.x * 128;
    const int n0 = blockIdx.y * 128;
    const uint32_t sb = smem_u32(tcsm);

    float acc[2][8][4];
    #pragma unroll
    for (int mt = 0; mt < 2; mt++)
        #pragma unroll
        for (int nt = 0; nt < 8; nt++)
            #pragma unroll
            for (int i = 0; i < 4; i++) acc[mt][nt][i] = 0.f;

    const int a_row  = lane & 15;
    const int a_colb = (lane >> 4) << 4;
    const int b_row  = ((lane >> 4) << 3) + (lane & 7);
    const int b_colb = ((lane >> 3) & 1) << 4;

    #pragma unroll 1
    for (int kc = 0; kc < 8; kc++) {
        #pragma unroll
        for (int it = 0; it < 8; it++) {
            int e = tid + it * 256;
            int row = e >> 4, kq = e & 15;
            int so = GSWZ(row * 128 + kq * 8);
            ull hb, lb;
            float4 a = *reinterpret_cast<const float4*>(&A[(size_t)(m0 + row) * DM + kc * 64 + kq * 4]);
            split4(a, hb, lb);
            *reinterpret_cast<ull*>(tcsm + TCB_AH + so) = hb;
            *reinterpret_cast<ull*>(tcsm + TCB_AL + so) = lb;
            float4 w = *reinterpret_cast<const float4*>(&W[(size_t)(n0 + row) * DM + kc * 64 + kq * 4]);
            split4(w, hb, lb);
            *reinterpret_cast<ull*>(tcsm + TCB_WH + so) = hb;
            *reinterpret_cast<ull*>(tcsm + TCB_WL + so) = lb;
        }
        __syncthreads();

        #pragma unroll
        for (int k16 = 0; k16 < 4; k16++) {
            const int kb = k16 * 32;
            uint32_t ah[2][4], al[2][4];
            #pragma unroll
            for (int mt = 0; mt < 2; mt++) {
                int ro = (wr * 32 + mt * 16 + a_row) * 128 + kb + a_colb;
                uint32_t ad = sb + GSWZ(ro);
                LDM_X4(ah[mt], ad + TCB_AH);
                LDM_X4(al[mt], ad + TCB_AL);
            }
            #pragma unroll
            for (int p = 0; p < 4; p++) {
                int ro = (wc * 64 + p * 16 + b_row) * 128 + kb + b_colb;
                uint32_t bd = sb + GSWZ(ro);
                uint32_t bh[4], bl[4];
                LDM_X4(bh, bd + TCB_WH);
                LDM_X4(bl, bd + TCB_WL);
                #pragma unroll
                for (int mt = 0; mt < 2; mt++) {
                    mma16816(acc[mt][2 * p],     ah[mt], bh[0], bh[1]);
                    mma16816(acc[mt][2 * p],     ah[mt], bl[0], bl[1]);
                    mma16816(acc[mt][2 * p],     al[mt], bh[0], bh[1]);
                    mma16816(acc[mt][2 * p + 1], ah[mt], bh[2], bh[3]);
                    mma16816(acc[mt][2 * p + 1], ah[mt], bl[2], bl[3]);
                    mma16816(acc[mt][2 * p + 1], al[mt], bh[2], bh[3]);
                }
            }
        }
        __syncthreads();
    }

    const int g = lane >> 2, t2 = (lane & 3) << 1;
    #pragma unroll
    for (int nt = 0; nt < 8; nt++) {
        int col = n0 + wc * 64 + nt * 8 + t2;
        float b0 = bias[col], b1 = bias[col + 1];
        #pragma unroll
        for (int mt = 0; mt < 2; mt++) {
            int row = m0 + wr * 32 + mt * 16 + g;
            float v00 = acc[mt][nt][0] + b0, v01 = acc[mt][nt][1] + b1;
            float v10 = acc[mt][nt][2] + b0, v11 = acc[mt][nt][3] + b1;
            if (MODE == 0) {
                *reinterpret_cast<float2*>(&C[(size_t)row * DM + col])       = make_float2(v00, v01);
                *reinterpret_cast<float2*>(&C[(size_t)(row + 8) * DM + col]) = make_float2(v10, v11);
            } else {
                v00 *= scale; v01 *= scale; v10 *= scale; v11 *= scale;
                uint32_t ph, pl;
                splitp(v00, v01, ph, pl);
                *reinterpret_cast<uint32_t*>(&Ch[(size_t)row * DM + col]) = ph;
                *reinterpret_cast<uint32_t*>(&Cl[(size_t)row * DM + col]) = pl;
                splitp(v10, v11, ph, pl);
                *reinterpret_cast<uint32_t*>(&Ch[(size_t)(row + 8) * DM + col]) = ph;
                *reinterpret_cast<uint32_t*>(&Cl[(size_t)(row + 8) * DM + col]) = pl;
            }
        }
    }
}

// =====================================================================
// Tensor-core flash attention (no-max softmax), split-KV.
// Inputs pre-split bf16 (hi/lo). CTA 128q, 64-key chunks, 8 warps 16q x 64k.
// Staging = pure bf16 copy (no conversion math).
// =====================================================================
#define AQH 0
#define AQL (AQH + 128 * 144)
#define AKH (AQL + 128 * 144)
#define AKL (AKH + 64 * 144)
#define AVH (AKL + 64 * 144)
#define AVL (AVH + 64 * 144)
#define ATTN_SMEM (AVL + 64 * 144)   // 73728 B -> 2 CTAs/SM

__global__ void __launch_bounds__(256, 2) attn_kernel(
    const __nv_bfloat16* __restrict__ Qh, const __nv_bfloat16* __restrict__ Ql,
    const __nv_bfloat16* __restrict__ Kh, const __nv_bfloat16* __restrict__ Kl,
    const __nv_bfloat16* __restrict__ Vh, const __nv_bfloat16* __restrict__ Vl)
{
    extern __shared__ __align__(1024) char smc[];
    const int tid = threadIdx.x;
    const int lane = tid & 31, wid = tid >> 5;
    const int bh = blockIdx.y;
    const int b = bh >> 3, h = bh & 7;
    const int q0 = blockIdx.x * 128;
    const int split = blockIdx.z;
    const int kbase = split * KPS;
    const uint32_t sb = smem_u32(smc);

    const size_t boff = (size_t)b * S_LEN * DM + (size_t)h * DH;
    const __nv_bfloat16* Qhb = Qh + boff;
    const __nv_bfloat16* Qlb = Ql + boff;
    const __nv_bfloat16* Khb = Kh + boff;
    const __nv_bfloat16* Klb = Kl + boff;
    const __nv_bfloat16* Vhb = Vh + boff;
    const __nv_bfloat16* Vlb = Vl + boff;

    // ---- stage Q (already scaled + split) : pure copy ----
    #pragma unroll
    for (int it = 0; it < 8; it++) {
        int e = tid + it * 256;
        int d4 = (e & 15) << 2, qq = e >> 4;
        size_t go = (size_t)(q0 + qq) * DM + d4;
        *reinterpret_cast<ull*>(smc + AQH + qq * 144 + d4 * 2) =
            *reinterpret_cast<const ull*>(&Qhb[go]);
        *reinterpret_cast<ull*>(smc + AQL + qq * 144 + d4 * 2) =
            *reinterpret_cast<const ull*>(&Qlb[go]);
    }

    float oacc[8][4];
    #pragma unroll
    for (int j = 0; j < 8; j++)
        #pragma unroll
        for (int i = 0; i < 4; i++) oacc[j][i] = 0.f;
    float lrow0 = 0.f, lrow1 = 0.f;

    const int a_row  = lane & 15;
    const int a_colb = (lane >> 4) << 4;
    const int kb_row  = ((lane >> 4) << 3) + (lane & 7);   // K (non-trans B)
    const int kb_colb = ((lane >> 3) & 1) << 4;
    const int vb_row  = lane & 15;                          // V (trans B)
    const int vb_colb = (lane >> 4) << 4;

    #pragma unroll 1
    for (int kt = 0; kt < KPS / 64; kt++) {
        const int kk0 = kbase + kt * 64;
        __syncthreads();   // prior PV done reading V; K free
        #pragma unroll
        for (int it = 0; it < 4; it++) {
            int e = tid + it * 256;
            int d4 = (e & 15) << 2, r = e >> 4;
            size_t go = (size_t)(kk0 + r) * DM + d4;
            *reinterpret_cast<ull*>(smc + AKH + r * 144 + d4 * 2) =
                *reinterpret_cast<const ull*>(&Khb[go]);
            *reinterpret_cast<ull*>(smc + AKL + r * 144 + d4 * 2) =
                *reinterpret_cast<const ull*>(&Klb[go]);
            *reinterpret_cast<ull*>(smc + AVH + r * 144 + d4 * 2) =
                *reinterpret_cast<const ull*>(&Vhb[go]);
            *reinterpret_cast<ull*>(smc + AVL + r * 144 + d4 * 2) =
                *reinterpret_cast<const ull*>(&Vlb[go]);
        }
        __syncthreads();

        // ---- S = Q @ K^T (3-term split) : 16q x 64k per warp ----
        float sacc[8][4];
        #pragma unroll
        for (int j = 0; j < 8; j++)
            #pragma unroll
            for (int i = 0; i < 4; i++) sacc[j][i] = 0.f;

        #pragma unroll
        for (int k16 = 0; k16 < 4; k16++) {
            uint32_t qa = sb + (wid * 16 + a_row) * 144 + k16 * 32 + a_colb;
            uint32_t ah[4], al[4];
            LDM_X4(ah, qa + AQH);
            LDM_X4(al, qa + AQL);
            #pragma unroll
            for (int p = 0; p < 4; p++) {
                uint32_t ka = sb + (p * 16 + kb_row) * 144 + k16 * 32 + kb_colb;
                uint32_t bh[4], bl[4];
                LDM_X4(bh, ka + AKH);
                LDM_X4(bl, ka + AKL);
                mma16816(sacc[2 * p],     ah, bh[0], bh[1]);
                mma16816(sacc[2 * p],     ah, bl[0], bl[1]);
                mma16816(sacc[2 * p],     al, bh[0], bh[1]);
                mma16816(sacc[2 * p + 1], ah, bh[2], bh[3]);
                mma16816(sacc[2 * p + 1], ah, bl[2], bl[3]);
                mma16816(sacc[2 * p + 1], al, bh[2], bh[3]);
            }
        }

        // ---- P = exp(S) in place; accumulate l ----
        #pragma unroll
        for (int j = 0; j < 8; j++) {
            sacc[j][0] = __expf(sacc[j][0]);
            sacc[j][1] = __expf(sacc[j][1]);
            sacc[j][2] = __expf(sacc[j][2]);
            sacc[j][3] = __expf(sacc[j][3]);
            lrow0 += sacc[j][0] + sacc[j][1];
            lrow1 += sacc[j][2] + sacc[j][3];
        }

        // ---- O += P @ V (P split 2, V split 2; 3 terms) ----
        #pragma unroll
        for (int kq = 0; kq < 4; kq++) {
            const float* t0 = sacc[2 * kq];
            const float* t1 = sacc[2 * kq + 1];
            uint32_t pah[4], pal[4];
            splitp(t0[0], t0[1], pah[0], pal[0]);
            splitp(t0[2], t0[3], pah[1], pal[1]);
            splitp(t1[0], t1[1], pah[2], pal[2]);
            splitp(t1[2], t1[3], pah[3], pal[3]);
            #pragma unroll
            for (int p = 0; p < 4; p++) {
                uint32_t va = sb + (kq * 16 + vb_row) * 144 + p * 32 + vb_colb;
                uint32_t vh[4], vl[4];
                LDM_X4_T(vh, va + AVH);
                LDM_X4_T(vl, va + AVL);
                mma16816(oacc[2 * p],     pah, vh[0], vh[1]);
                mma16816(oacc[2 * p],     pah, vl[0], vl[1]);
                mma16816(oacc[2 * p],     pal, vh[0], vh[1]);
                mma16816(oacc[2 * p + 1], pah, vh[2], vh[3]);
                mma16816(oacc[2 * p + 1], pah, vl[2], vl[3]);
                mma16816(oacc[2 * p + 1], pal, vh[2], vh[3]);
            }
        }
    }

    // ---- epilogue ----
    const int g = lane >> 2, t4 = lane & 3;
    #pragma unroll
    for (int off = 1; off < 4; off <<= 1) {
        lrow0 += __shfl_xor_sync(0xffffffffu, lrow0, off);
        lrow1 += __shfl_xor_sync(0xffffffffu, lrow1, off);
    }

    float* Ob = g_opart + ((((size_t)split * B_SZ + b) * HN + h) * S_LEN + q0) * DH;
    const int r0 = wid * 16 + g, r1 = r0 + 8;
    #pragma unroll
    for (int j = 0; j < 8; j++) {
        int col = j * 8 + t4 * 2;
        *reinterpret_cast<float2*>(&Ob[(size_t)r0 * DH + col]) = make_float2(oacc[j][0], oacc[j][1]);
        *reinterpret_cast<float2*>(&Ob[(size_t)r1 * DH + col]) = make_float2(oacc[j][2], oacc[j][3]);
    }
    if (t4 == 0) {
        float* Lb = g_l + ((size_t)(split * B_SZ + b) * HN + h) * S_LEN + q0;
        Lb[r0] = lrow0;
        Lb[r1] = lrow1;
    }
}

// =====================================================================
// Merge split-KV partials: ctx[b][q][h*64+dv] = sum_s O_s / sum_s l_s
// =====================================================================
__global__ void __launch_bounds__(256) merge_kernel()
{
    int idx = blockIdx.x * 256 + threadIdx.x;
    int dv4 = (idx & 15) << 2;
    int q   = (idx >> 4) & 4095;
    int h   = (idx >> 16) & 7;
    int b   = idx >> 19;

    float sx = 0.f, sy = 0.f, sz = 0.f, sw = 0.f, lsum = 0.f;
    #pragma unroll
    for (int s = 0; s < NSPLIT; s++) {
        size_t ob = ((((size_t)s * B_SZ + b) * HN + h) * S_LEN + q) * DH + dv4;
        float4 v = *reinterpret_cast<const float4*>(&g_opart[ob]);
        sx += v.x; sy += v.y; sz += v.z; sw += v.w;
        lsum += g_l[((size_t)(s * B_SZ + b) * HN + h) * S_LEN + q];
    }
    float inv = 1.0f / lsum;
    size_t co = ((size_t)b * S_LEN + q) * DM + h * DH + dv4;
    *reinterpret_cast<float4*>(&g_ctx[co]) = make_float4(sx * inv, sy * inv, sz * inv, sw * inv);
}

// =====================================================================
extern "C" void kernel_launch(void* const* d_in, const int* in_sizes, int n_in,
                              void* d_out, int out_size)
{
    const float* q  = (const float*)d_in[0];
    const float* k  = (const float*)d_in[1];
    const float* v  = (const float*)d_in[2];
    const float* Wq = (const float*)d_in[3];
    const float* bq = (const float*)d_in[4];
    const float* Wk = (const float*)d_in[5];
    const float* bk = (const float*)d_in[6];
    const float* Wv = (const float*)d_in[7];
    const float* bv = (const float*)d_in[8];
    const float* Wo = (const float*)d_in[9];
    const float* bo = (const float*)d_in[10];
    float* out = (float*)d_out;

    __nv_bfloat16 *gqh, *gql, *gkh, *gkl, *gvh, *gvl;
    float *gctx;
    cudaGetSymbolAddress((void**)&gqh, g_qh);
    cudaGetSymbolAddress((void**)&gql, g_ql);
    cudaGetSymbolAddress((void**)&gkh, g_kh);
    cudaGetSymbolAddress((void**)&gkl, g_kl);
    cudaGetSymbolAddress((void**)&gvh, g_vh);
    cudaGetSymbolAddress((void**)&gvl, g_vl);
    cudaGetSymbolAddress((void**)&gctx, g_ctx);

    cudaFuncSetAttribute(attn_kernel, cudaFuncAttributeMaxDynamicSharedMemorySize, ATTN_SMEM);
    cudaFuncSetAttribute(tc_gemm_kernel<0>, cudaFuncAttributeMaxDynamicSharedMemorySize, TC_SMEM);
    cudaFuncSetAttribute(tc_gemm_kernel<1>, cudaFuncAttributeMaxDynamicSharedMemorySize, TC_SMEM);

    dim3 ggrid(64, 4);   // (8192/128, 512/128)
    tc_gemm_kernel<1><<<ggrid, 256, TC_SMEM>>>(q, Wq, bq, nullptr, gqh, gql, 0.125f);
    tc_gemm_kernel<1><<<ggrid, 256, TC_SMEM>>>(k, Wk, bk, nullptr, gkh, gkl, 1.0f);
    tc_gemm_kernel<1><<<ggrid, 256, TC_SMEM>>>(v, Wv, bv, nullptr, gvh, gvl, 1.0f);

    dim3 agrid(S_LEN / 128, B_SZ * HN, NSPLIT);   // (32, 16, 4)
    attn_kernel<<<agrid, 256, ATTN_SMEM>>>(gqh, gql, gkh, gkl, gvh, gvl);

    merge_kernel<<<(B_SZ * HN * S_LEN * (DH / 4)) / 256, 256>>>();   // 8192 blocks

    tc_gemm_kernel<0><<<ggrid, 256, TC_SMEM>>>(gctx, Wo, bo, out, nullptr, nullptr, 1.0f);
}

// round 15
// speedup vs baseline: 2.6784x; 1.0628x over previous
#include <cuda_runtime.h>
#include <cuda_bf16.h>
#include <cstdint>

#define S_LEN 4096
#define B_SZ  2
#define DM    512
#define HN    8
#define DH    64
#define NSPLIT 4
#define KPS   (S_LEN / NSPLIT)   // 1024 keys per split
#define BSD   ((size_t)B_SZ * S_LEN * DM)

typedef unsigned long long ull;

// ---------------- mma.sync helpers (baseline PTX, works under compute_103) ----
#define GSWZ(o) ((o) ^ (((o) >> 3) & 0x70))

__device__ __forceinline__ uint32_t smem_u32(const void* p) {
    uint32_t a;
    asm("{ .reg .u64 t; cvta.to.shared.u64 t, %1; cvt.u32.u64 %0, t; }" : "=r"(a) : "l"(p));
    return a;
}
#define LDM_X4(r, addr)                                                        \
    asm volatile("ldmatrix.sync.aligned.m8n8.x4.shared.b16 {%0,%1,%2,%3}, [%4];" \
        : "=r"((r)[0]), "=r"((r)[1]), "=r"((r)[2]), "=r"((r)[3]) : "r"(addr))
#define LDM_X4_T(r, addr)                                                      \
    asm volatile("ldmatrix.sync.aligned.m8n8.x4.trans.shared.b16 {%0,%1,%2,%3}, [%4];" \
        : "=r"((r)[0]), "=r"((r)[1]), "=r"((r)[2]), "=r"((r)[3]) : "r"(addr))

__device__ __forceinline__ void mma16816(float* d, const uint32_t* a, uint32_t b0, uint32_t b1) {
    asm volatile(
        "mma.sync.aligned.m16n8k16.row.col.f32.bf16.bf16.f32 "
        "{%0,%1,%2,%3}, {%4,%5,%6,%7}, {%8,%9}, {%0,%1,%2,%3};"
        : "+f"(d[0]), "+f"(d[1]), "+f"(d[2]), "+f"(d[3])
        : "r"(a[0]), "r"(a[1]), "r"(a[2]), "r"(a[3]), "r"(b0), "r"(b1));
}
// pack {lo, hi} floats to bf16x2 (lo in bits 15:0)
__device__ __forceinline__ uint32_t cvt2(float hi, float lo) {
    uint32_t r; asm("cvt.rn.bf16x2.f32 %0, %1, %2;" : "=r"(r) : "f"(hi), "f"(lo)); return r;
}
// split pair (d0,d1) into hi bf16x2 + residual-lo bf16x2
__device__ __forceinline__ void splitp(float d0, float d1, uint32_t& ph, uint32_t& pl) {
    ph = cvt2(d1, d0);
    float h0 = __uint_as_float(ph << 16);
    float h1 = __uint_as_float(ph & 0xffff0000u);
    pl = cvt2(d1 - h1, d0 - h0);
}
// split a float4 into hi/lo bf16 quads (packed as 4x16-bit in a ull)
__device__ __forceinline__ void split4(float4 a, ull& hb, ull& lb) {
    uint32_t h0, l0, h1, l1;
    splitp(a.x, a.y, h0, l0);
    splitp(a.z, a.w, h1, l1);
    hb = (ull)h0 | ((ull)h1 << 32);
    lb = (ull)l0 | ((ull)l1 << 32);
}

// ---------------- scratch (no cudaMalloc allowed) ----------------
// pre-split inputs (q,k,v) and weights (Wq,Wk,Wv,Wo)
__device__ __nv_bfloat16 g_inh[3][BSD];
__device__ __nv_bfloat16 g_inl[3][BSD];
__device__ __nv_bfloat16 g_wh[4][DM * DM];
__device__ __nv_bfloat16 g_wl[4][DM * DM];
// projected Q/K/V (split, Q pre-scaled)
__device__ __nv_bfloat16 g_qh[BSD];
__device__ __nv_bfloat16 g_ql[BSD];
__device__ __nv_bfloat16 g_kh[BSD];
__device__ __nv_bfloat16 g_kl[BSD];
__device__ __nv_bfloat16 g_vh[BSD];
__device__ __nv_bfloat16 g_vl[BSD];
// merged context (split)
__device__ __nv_bfloat16 g_ctxh[BSD];
__device__ __nv_bfloat16 g_ctxl[BSD];
__device__ float g_opart[(size_t)NSPLIT * BSD];   // unnormalized per-split O
__device__ float g_l[NSPLIT * B_SZ * HN * S_LEN]; // per-split softmax denominators

// =====================================================================
// presplit: fp32 -> (hi, lo residual) bf16 arrays. One float4 per thread.
// =====================================================================
__global__ void __launch_bounds__(256) presplit_kernel(
    const float* __restrict__ src, __nv_bfloat16* __restrict__ h,
    __nv_bfloat16* __restrict__ l, int n4)
{
    int i = blockIdx.x * 256 + threadIdx.x;
    if (i >= n4) return;
    float4 v = *reinterpret_cast<const float4*>(src + (size_t)i * 4);
    ull hb, lb;
    split4(v, hb, lb);
    *reinterpret_cast<ull*>(&h[(size_t)i * 4]) = hb;
    *reinterpret_cast<ull*>(&l[(size_t)i * 4]) = lb;
}

// =====================================================================
// Tensor-core GEMM via mma.sync (3-term split), PRE-SPLIT bf16 operands.
// Staging = pure bf16 copy. MODE 0: fp32 C out. MODE 1: split bf16 out
// (Ch, Cl) with pre-scale applied before the split.
// =====================================================================
#define TCB_AH 0
#define TCB_AL 16384
#define TCB_WH 32768
#define TCB_WL 49152
#define TC_SMEM 65536

template<int MODE>
__global__ void __launch_bounds__(256) tc_gemm_kernel(
    const __nv_bfloat16* __restrict__ Ah, const __nv_bfloat16* __restrict__ Al,
    const __nv_bfloat16* __restrict__ Wh, const __nv_bfloat16* __restrict__ Wl,
    const float* __restrict__ bias, float* __restrict__ C,
    __nv_bfloat16* __restrict__ Ch, __nv_bfloat16* __restrict__ Cl, float scale)
{
    extern __shared__ __align__(1024) char tcsm[];
    const int tid = threadIdx.x;
    const int lane = tid & 31, wid = tid >> 5;
    const int wr = wid >> 1, wc = wid & 1;
    const int m0 = blockIdx.x * 128;
    const int n0 = blockIdx.y * 128;
    const uint32_t sb = smem_u32(tcsm);

    float acc[2][8][4];
    #pragma unroll
    for (int mt = 0; mt < 2; mt++)
        #pragma unroll
        for (int nt = 0; nt < 8; nt++)
            #pragma unroll
            for (int i = 0; i < 4; i++) acc[mt][nt][i] = 0.f;

    const int a_row  = lane & 15;
    const int a_colb = (lane >> 4) << 4;
    const int b_row  = ((lane >> 4) << 3) + (lane & 7);
    const int b_colb = ((lane >> 3) & 1) << 4;

    #pragma unroll 1
    for (int kc = 0; kc < 8; kc++) {
        // ---- stage A/W chunk (128 rows x 64 k) : pure bf16 copy ----
        #pragma unroll
        for (int it = 0; it < 8; it++) {
            int e = tid + it * 256;
            int row = e >> 4, kq = e & 15;
            int so = GSWZ(row * 128 + kq * 8);
            size_t go = (size_t)(m0 + row) * DM + kc * 64 + kq * 4;
            size_t gw = (size_t)(n0 + row) * DM + kc * 64 + kq * 4;
            *reinterpret_cast<ull*>(tcsm + TCB_AH + so) = *reinterpret_cast<const ull*>(&Ah[go]);
            *reinterpret_cast<ull*>(tcsm + TCB_AL + so) = *reinterpret_cast<const ull*>(&Al[go]);
            *reinterpret_cast<ull*>(tcsm + TCB_WH + so) = *reinterpret_cast<const ull*>(&Wh[gw]);
            *reinterpret_cast<ull*>(tcsm + TCB_WL + so) = *reinterpret_cast<const ull*>(&Wl[gw]);
        }
        __syncthreads();

        #pragma unroll
        for (int k16 = 0; k16 < 4; k16++) {
            const int kb = k16 * 32;
            uint32_t ah[2][4], al[2][4];
            #pragma unroll
            for (int mt = 0; mt < 2; mt++) {
                int ro = (wr * 32 + mt * 16 + a_row) * 128 + kb + a_colb;
                uint32_t ad = sb + GSWZ(ro);
                LDM_X4(ah[mt], ad + TCB_AH);
                LDM_X4(al[mt], ad + TCB_AL);
            }
            #pragma unroll
            for (int p = 0; p < 4; p++) {
                int ro = (wc * 64 + p * 16 + b_row) * 128 + kb + b_colb;
                uint32_t bd = sb + GSWZ(ro);
                uint32_t bh[4], bl[4];
                LDM_X4(bh, bd + TCB_WH);
                LDM_X4(bl, bd + TCB_WL);
                #pragma unroll
                for (int mt = 0; mt < 2; mt++) {
                    mma16816(acc[mt][2 * p],     ah[mt], bh[0], bh[1]);
                    mma16816(acc[mt][2 * p],     ah[mt], bl[0], bl[1]);
                    mma16816(acc[mt][2 * p],     al[mt], bh[0], bh[1]);
                    mma16816(acc[mt][2 * p + 1], ah[mt], bh[2], bh[3]);
                    mma16816(acc[mt][2 * p + 1], ah[mt], bl[2], bl[3]);
                    mma16816(acc[mt][2 * p + 1], al[mt], bh[2], bh[3]);
                }
            }
        }
        __syncthreads();
    }

    const int g = lane >> 2, t2 = (lane & 3) << 1;
    #pragma unroll
    for (int nt = 0; nt < 8; nt++) {
        int col = n0 + wc * 64 + nt * 8 + t2;
        float b0 = bias[col], b1 = bias[col + 1];
        #pragma unroll
        for (int mt = 0; mt < 2; mt++) {
            int row = m0 + wr * 32 + mt * 16 + g;
            float v00 = acc[mt][nt][0] + b0, v01 = acc[mt][nt][1] + b1;
            float v10 = acc[mt][nt][2] + b0, v11 = acc[mt][nt][3] + b1;
            if (MODE == 0) {
                *reinterpret_cast<float2*>(&C[(size_t)row * DM + col])       = make_float2(v00, v01);
                *reinterpret_cast<float2*>(&C[(size_t)(row + 8) * DM + col]) = make_float2(v10, v11);
            } else {
                v00 *= scale; v01 *= scale; v10 *= scale; v11 *= scale;
                uint32_t ph, pl;
                splitp(v00, v01, ph, pl);
                *reinterpret_cast<uint32_t*>(&Ch[(size_t)row * DM + col]) = ph;
                *reinterpret_cast<uint32_t*>(&Cl[(size_t)row * DM + col]) = pl;
                splitp(v10, v11, ph, pl);
                *reinterpret_cast<uint32_t*>(&Ch[(size_t)(row + 8) * DM + col]) = ph;
                *reinterpret_cast<uint32_t*>(&Cl[(size_t)(row + 8) * DM + col]) = pl;
            }
        }
    }
}

// =====================================================================
// Tensor-core flash attention (no-max softmax), split-KV. R13-exact.
// =====================================================================
#define AQH 0
#define AQL (AQH + 128 * 144)
#define AKH (AQL + 128 * 144)
#define AKL (AKH + 64 * 144)
#define AVH (AKL + 64 * 144)
#define AVL (AVH + 64 * 144)
#define ATTN_SMEM (AVL + 64 * 144)   // 73728 B -> 2 CTAs/SM

__global__ void __launch_bounds__(256, 2) attn_kernel(
    const __nv_bfloat16* __restrict__ Qh, const __nv_bfloat16* __restrict__ Ql,
    const __nv_bfloat16* __restrict__ Kh, const __nv_bfloat16* __restrict__ Kl,
    const __nv_bfloat16* __restrict__ Vh, const __nv_bfloat16* __restrict__ Vl)
{
    extern __shared__ __align__(1024) char smc[];
    const int tid = threadIdx.x;
    const int lane = tid & 31, wid = tid >> 5;
    const int bh = blockIdx.y;
    const int b = bh >> 3, h = bh & 7;
    const int q0 = blockIdx.x * 128;
    const int split = blockIdx.z;
    const int kbase = split * KPS;
    const uint32_t sb = smem_u32(smc);

    const size_t boff = (size_t)b * S_LEN * DM + (size_t)h * DH;
    const __nv_bfloat16* Qhb = Qh + boff;
    const __nv_bfloat16* Qlb = Ql + boff;
    const __nv_bfloat16* Khb = Kh + boff;
    const __nv_bfloat16* Klb = Kl + boff;
    const __nv_bfloat16* Vhb = Vh + boff;
    const __nv_bfloat16* Vlb = Vl + boff;

    // ---- stage Q (already scaled + split) : pure copy ----
    #pragma unroll
    for (int it = 0; it < 8; it++) {
        int e = tid + it * 256;
        int d4 = (e & 15) << 2, qq = e >> 4;
        size_t go = (size_t)(q0 + qq) * DM + d4;
        *reinterpret_cast<ull*>(smc + AQH + qq * 144 + d4 * 2) =
            *reinterpret_cast<const ull*>(&Qhb[go]);
        *reinterpret_cast<ull*>(smc + AQL + qq * 144 + d4 * 2) =
            *reinterpret_cast<const ull*>(&Qlb[go]);
    }

    float oacc[8][4];
    #pragma unroll
    for (int j = 0; j < 8; j++)
        #pragma unroll
        for (int i = 0; i < 4; i++) oacc[j][i] = 0.f;
    float lrow0 = 0.f, lrow1 = 0.f;

    const int a_row  = lane & 15;
    const int a_colb = (lane >> 4) << 4;
    const int kb_row  = ((lane >> 4) << 3) + (lane & 7);   // K (non-trans B)
    const int kb_colb = ((lane >> 3) & 1) << 4;
    const int vb_row  = lane & 15;                          // V (trans B)
    const int vb_colb = (lane >> 4) << 4;

    #pragma unroll 1
    for (int kt = 0; kt < KPS / 64; kt++) {
        const int kk0 = kbase + kt * 64;
        __syncthreads();   // prior PV done reading V; K free
        #pragma unroll
        for (int it = 0; it < 4; it++) {
            int e = tid + it * 256;
            int d4 = (e & 15) << 2, r = e >> 4;
            size_t go = (size_t)(kk0 + r) * DM + d4;
            *reinterpret_cast<ull*>(smc + AKH + r * 144 + d4 * 2) =
                *reinterpret_cast<const ull*>(&Khb[go]);
            *reinterpret_cast<ull*>(smc + AKL + r * 144 + d4 * 2) =
                *reinterpret_cast<const ull*>(&Klb[go]);
            *reinterpret_cast<ull*>(smc + AVH + r * 144 + d4 * 2) =
                *reinterpret_cast<const ull*>(&Vhb[go]);
            *reinterpret_cast<ull*>(smc + AVL + r * 144 + d4 * 2) =
                *reinterpret_cast<const ull*>(&Vlb[go]);
        }
        __syncthreads();

        // ---- S = Q @ K^T (3-term split) : 16q x 64k per warp ----
        float sacc[8][4];
        #pragma unroll
        for (int j = 0; j < 8; j++)
            #pragma unroll
            for (int i = 0; i < 4; i++) sacc[j][i] = 0.f;

        #pragma unroll
        for (int k16 = 0; k16 < 4; k16++) {
            uint32_t qa = sb + (wid * 16 + a_row) * 144 + k16 * 32 + a_colb;
            uint32_t ah[4], al[4];
            LDM_X4(ah, qa + AQH);
            LDM_X4(al, qa + AQL);
            #pragma unroll
            for (int p = 0; p < 4; p++) {
                uint32_t ka = sb + (p * 16 + kb_row) * 144 + k16 * 32 + kb_colb;
                uint32_t bh[4], bl[4];
                LDM_X4(bh, ka + AKH);
                LDM_X4(bl, ka + AKL);
                mma16816(sacc[2 * p],     ah, bh[0], bh[1]);
                mma16816(sacc[2 * p],     ah, bl[0], bl[1]);
                mma16816(sacc[2 * p],     al, bh[0], bh[1]);
                mma16816(sacc[2 * p + 1], ah, bh[2], bh[3]);
                mma16816(sacc[2 * p + 1], ah, bl[2], bl[3]);
                mma16816(sacc[2 * p + 1], al, bh[2], bh[3]);
            }
        }

        // ---- P = exp(S) in place; accumulate l ----
        #pragma unroll
        for (int j = 0; j < 8; j++) {
            sacc[j][0] = __expf(sacc[j][0]);
            sacc[j][1] = __expf(sacc[j][1]);
            sacc[j][2] = __expf(sacc[j][2]);
            sacc[j][3] = __expf(sacc[j][3]);
            lrow0 += sacc[j][0] + sacc[j][1];
            lrow1 += sacc[j][2] + sacc[j][3];
        }

        // ---- O += P @ V (P split 2, V split 2; 3 terms) ----
        #pragma unroll
        for (int kq = 0; kq < 4; kq++) {
            const float* t0 = sacc[2 * kq];
            const float* t1 = sacc[2 * kq + 1];
            uint32_t pah[4], pal[4];
            splitp(t0[0], t0[1], pah[0], pal[0]);
            splitp(t0[2], t0[3], pah[1], pal[1]);
            splitp(t1[0], t1[1], pah[2], pal[2]);
            splitp(t1[2], t1[3], pah[3], pal[3]);
            #pragma unroll
            for (int p = 0; p < 4; p++) {
                uint32_t va = sb + (kq * 16 + vb_row) * 144 + p * 32 + vb_colb;
                uint32_t vh[4], vl[4];
                LDM_X4_T(vh, va + AVH);
                LDM_X4_T(vl, va + AVL);
                mma16816(oacc[2 * p],     pah, vh[0], vh[1]);
                mma16816(oacc[2 * p],     pah, vl[0], vl[1]);
                mma16816(oacc[2 * p],     pal, vh[0], vh[1]);
                mma16816(oacc[2 * p + 1], pah, vh[2], vh[3]);
                mma16816(oacc[2 * p + 1], pah, vl[2], vl[3]);
                mma16816(oacc[2 * p + 1], pal, vh[2], vh[3]);
            }
        }
    }

    // ---- epilogue ----
    const int g = lane >> 2, t4 = lane & 3;
    #pragma unroll
    for (int off = 1; off < 4; off <<= 1) {
        lrow0 += __shfl_xor_sync(0xffffffffu, lrow0, off);
        lrow1 += __shfl_xor_sync(0xffffffffu, lrow1, off);
    }

    float* Ob = g_opart + ((((size_t)split * B_SZ + b) * HN + h) * S_LEN + q0) * DH;
    const int r0 = wid * 16 + g, r1 = r0 + 8;
    #pragma unroll
    for (int j = 0; j < 8; j++) {
        int col = j * 8 + t4 * 2;
        *reinterpret_cast<float2*>(&Ob[(size_t)r0 * DH + col]) = make_float2(oacc[j][0], oacc[j][1]);
        *reinterpret_cast<float2*>(&Ob[(size_t)r1 * DH + col]) = make_float2(oacc[j][2], oacc[j][3]);
    }
    if (t4 == 0) {
        float* Lb = g_l + ((size_t)(split * B_SZ + b) * HN + h) * S_LEN + q0;
        Lb[r0] = lrow0;
        Lb[r1] = lrow1;
    }
}

// =====================================================================
// Merge split-KV partials -> pre-split bf16 context (h/l).
// =====================================================================
__global__ void __launch_bounds__(256) merge_kernel()
{
    int idx = blockIdx.x * 256 + threadIdx.x;
    int dv4 = (idx & 15) << 2;
    int q   = (idx >> 4) & 4095;
    int h   = (idx >> 16) & 7;
    int b   = idx >> 19;

    float sx = 0.f, sy = 0.f, sz = 0.f, sw = 0.f, lsum = 0.f;
    #pragma unroll
    for (int s = 0; s < NSPLIT; s++) {
        size_t ob = ((((size_t)s * B_SZ + b) * HN + h) * S_LEN + q) * DH + dv4;
        float4 v = *reinterpret_cast<const float4*>(&g_opart[ob]);
        sx += v.x; sy += v.y; sz += v.z; sw += v.w;
        lsum += g_l[((size_t)(s * B_SZ + b) * HN + h) * S_LEN + q];
    }
    float inv = 1.0f / lsum;
    uint32_t h0, l0, h1, l1;
    splitp(sx * inv, sy * inv, h0, l0);
    splitp(sz * inv, sw * inv, h1, l1);
    size_t co = ((size_t)b * S_LEN + q) * DM + h * DH + dv4;
    *reinterpret_cast<ull*>(&g_ctxh[co]) = (ull)h0 | ((ull)h1 << 32);
    *reinterpret_cast<ull*>(&g_ctxl[co]) = (ull)l0 | ((ull)l1 << 32);
}

// =====================================================================
extern "C" void kernel_launch(void* const* d_in, const int* in_sizes, int n_in,
                              void* d_out, int out_size)
{
    const float* q  = (const float*)d_in[0];
    const float* k  = (const float*)d_in[1];
    const float* v  = (const float*)d_in[2];
    const float* Wq = (const float*)d_in[3];
    const float* bq = (const float*)d_in[4];
    const float* Wk = (const float*)d_in[5];
    const float* bk = (const float*)d_in[6];
    const float* Wv = (const float*)d_in[7];
    const float* bv = (const float*)d_in[8];
    const float* Wo = (const float*)d_in[9];
    const float* bo = (const float*)d_in[10];
    float* out = (float*)d_out;

    __nv_bfloat16 *inh[3], *inl[3], *wh[4], *wl[4];
    __nv_bfloat16 *gqh, *gql, *gkh, *gkl, *gvh, *gvl, *gctxh, *gctxl;
    {
        __nv_bfloat16 *p;
        cudaGetSymbolAddress((void**)&p, g_inh);
        inh[0] = p; inh[1] = p + BSD; inh[2] = p + 2 * BSD;
        cudaGetSymbolAddress((void**)&p, g_inl);
        inl[0] = p; inl[1] = p + BSD; inl[2] = p + 2 * BSD;
        cudaGetSymbolAddress((void**)&p, g_wh);
        wh[0] = p; wh[1] = p + DM * DM; wh[2] = p + 2 * DM * DM; wh[3] = p + 3 * DM * DM;
        cudaGetSymbolAddress((void**)&p, g_wl);
        wl[0] = p; wl[1] = p + DM * DM; wl[2] = p + 2 * DM * DM; wl[3] = p + 3 * DM * DM;
    }
    cudaGetSymbolAddress((void**)&gqh, g_qh);
    cudaGetSymbolAddress((void**)&gql, g_ql);
    cudaGetSymbolAddress((void**)&gkh, g_kh);
    cudaGetSymbolAddress((void**)&gkl, g_kl);
    cudaGetSymbolAddress((void**)&gvh, g_vh);
    cudaGetSymbolAddress((void**)&gvl, g_vl);
    cudaGetSymbolAddress((void**)&gctxh, g_ctxh);
    cudaGetSymbolAddress((void**)&gctxl, g_ctxl);

    cudaFuncSetAttribute(attn_kernel, cudaFuncAttributeMaxDynamicSharedMemorySize, ATTN_SMEM);
    cudaFuncSetAttribute(tc_gemm_kernel<0>, cudaFuncAttributeMaxDynamicSharedMemorySize, TC_SMEM);
    cudaFuncSetAttribute(tc_gemm_kernel<1>, cudaFuncAttributeMaxDynamicSharedMemorySize, TC_SMEM);

    // ---- presplit inputs and weights ----
    const int IN4 = (int)(BSD / 4);          // 1048576
    const int W4  = DM * DM / 4;             // 65536
    presplit_kernel<<<IN4 / 256, 256>>>(q, inh[0], inl[0], IN4);
    presplit_kernel<<<IN4 / 256, 256>>>(k, inh[1], inl[1], IN4);
    presplit_kernel<<<IN4 / 256, 256>>>(v, inh[2], inl[2], IN4);
    presplit_kernel<<<W4 / 256, 256>>>(Wq, wh[0], wl[0], W4);
    presplit_kernel<<<W4 / 256, 256>>>(Wk, wh[1], wl[1], W4);
    presplit_kernel<<<W4 / 256, 256>>>(Wv, wh[2], wl[2], W4);
    presplit_kernel<<<W4 / 256, 256>>>(Wo, wh[3], wl[3], W4);

    // ---- projections (split bf16 out; Q pre-scaled by 1/8) ----
    dim3 ggrid(64, 4);
    tc_gemm_kernel<1><<<ggrid, 256, TC_SMEM>>>(inh[0], inl[0], wh[0], wl[0], bq, nullptr, gqh, gql, 0.125f);
    tc_gemm_kernel<1><<<ggrid, 256, TC_SMEM>>>(inh[1], inl[1], wh[1], wl[1], bk, nullptr, gkh, gkl, 1.0f);
    tc_gemm_kernel<1><<<ggrid, 256, TC_SMEM>>>(inh[2], inl[2], wh[2], wl[2], bv, nullptr, gvh, gvl, 1.0f);

    dim3 agrid(S_LEN / 128, B_SZ * HN, NSPLIT);   // (32, 16, 4)
    attn_kernel<<<agrid, 256, ATTN_SMEM>>>(gqh, gql, gkh, gkl, gvh, gvl);

    merge_kernel<<<(B_SZ * HN * S_LEN * (DH / 4)) / 256, 256>>>();   // 8192 blocks

    // ---- output projection (fp32 out) ----
    tc_gemm_kernel<0><<<ggrid, 256, TC_SMEM>>>(gctxh, gctxl, wh[3], wl[3], bo, out, nullptr, nullptr, 1.0f);
}

// round 16
// speedup vs baseline: 2.7434x; 1.0243x over previous
#include <cuda_runtime.h>
#include <cuda_bf16.h>
#include <cstdint>

#define S_LEN 4096
#define B_SZ  2
#define DM    512
#define HN    8
#define DH    64
#define NSPLIT 4
#define KPS   (S_LEN / NSPLIT)   // 1024 keys per split
#define BSD   ((size_t)B_SZ * S_LEN * DM)

typedef unsigned long long ull;

// ---------------- mma.sync helpers (baseline PTX, works under compute_103) ----
#define GSWZ(o) ((o) ^ (((o) >> 3) & 0x70))

__device__ __forceinline__ uint32_t smem_u32(const void* p) {
    uint32_t a;
    asm("{ .reg .u64 t; cvta.to.shared.u64 t, %1; cvt.u32.u64 %0, t; }" : "=r"(a) : "l"(p));
    return a;
}
#define LDM_X4(r, addr)                                                        \
    asm volatile("ldmatrix.sync.aligned.m8n8.x4.shared.b16 {%0,%1,%2,%3}, [%4];" \
        : "=r"((r)[0]), "=r"((r)[1]), "=r"((r)[2]), "=r"((r)[3]) : "r"(addr))
#define LDM_X4_T(r, addr)                                                      \
    asm volatile("ldmatrix.sync.aligned.m8n8.x4.trans.shared.b16 {%0,%1,%2,%3}, [%4];" \
        : "=r"((r)[0]), "=r"((r)[1]), "=r"((r)[2]), "=r"((r)[3]) : "r"(addr))
#define CP_ASYNC16(dst, src)                                                   \
    asm volatile("cp.async.cg.shared.global [%0], [%1], 16;" :: "r"(dst), "l"(src))
#define CP_COMMIT()  asm volatile("cp.async.commit_group;" ::: "memory")
#define CP_WAIT0()   asm volatile("cp.async.wait_group 0;" ::: "memory")

__device__ __forceinline__ void mma16816(float* d, const uint32_t* a, uint32_t b0, uint32_t b1) {
    asm volatile(
        "mma.sync.aligned.m16n8k16.row.col.f32.bf16.bf16.f32 "
        "{%0,%1,%2,%3}, {%4,%5,%6,%7}, {%8,%9}, {%0,%1,%2,%3};"
        : "+f"(d[0]), "+f"(d[1]), "+f"(d[2]), "+f"(d[3])
        : "r"(a[0]), "r"(a[1]), "r"(a[2]), "r"(a[3]), "r"(b0), "r"(b1));
}
// pack {lo, hi} floats to bf16x2 (lo in bits 15:0)
__device__ __forceinline__ uint32_t cvt2(float hi, float lo) {
    uint32_t r; asm("cvt.rn.bf16x2.f32 %0, %1, %2;" : "=r"(r) : "f"(hi), "f"(lo)); return r;
}
// split pair (d0,d1) into hi bf16x2 + residual-lo bf16x2
__device__ __forceinline__ void splitp(float d0, float d1, uint32_t& ph, uint32_t& pl) {
    ph = cvt2(d1, d0);
    float h0 = __uint_as_float(ph << 16);
    float h1 = __uint_as_float(ph & 0xffff0000u);
    pl = cvt2(d1 - h1, d0 - h0);
}
// split a float4 into hi/lo bf16 quads (packed as 4x16-bit in a ull)
__device__ __forceinline__ void split4(float4 a, ull& hb, ull& lb) {
    uint32_t h0, l0, h1, l1;
    splitp(a.x, a.y, h0, l0);
    splitp(a.z, a.w, h1, l1);
    hb = (ull)h0 | ((ull)h1 << 32);
    lb = (ull)l0 | ((ull)l1 << 32);
}

// ---------------- scratch (no cudaMalloc allowed) ----------------
__device__ __nv_bfloat16 g_inh[3][BSD];
__device__ __nv_bfloat16 g_inl[3][BSD];
__device__ __nv_bfloat16 g_wh[4][DM * DM];
__device__ __nv_bfloat16 g_wl[4][DM * DM];
__device__ __nv_bfloat16 g_qh[BSD];
__device__ __nv_bfloat16 g_ql[BSD];
__device__ __nv_bfloat16 g_kh[BSD];
__device__ __nv_bfloat16 g_kl[BSD];
__device__ __nv_bfloat16 g_vh[BSD];
__device__ __nv_bfloat16 g_vl[BSD];
__device__ __nv_bfloat16 g_ctxh[BSD];
__device__ __nv_bfloat16 g_ctxl[BSD];
__device__ float g_opart[(size_t)NSPLIT * BSD];   // unnormalized per-split O
__device__ float g_l[NSPLIT * B_SZ * HN * S_LEN]; // per-split softmax denominators

// =====================================================================
// presplit: fp32 -> (hi, lo residual) bf16 arrays. One float4 per thread.
// =====================================================================
__global__ void __launch_bounds__(256) presplit_kernel(
    const float* __restrict__ src, __nv_bfloat16* __restrict__ h,
    __nv_bfloat16* __restrict__ l, int n4)
{
    int i = blockIdx.x * 256 + threadIdx.x;
    if (i >= n4) return;
    float4 v = *reinterpret_cast<const float4*>(src + (size_t)i * 4);
    ull hb, lb;
    split4(v, hb, lb);
    *reinterpret_cast<ull*>(&h[(size_t)i * 4]) = hb;
    *reinterpret_cast<ull*>(&l[(size_t)i * 4]) = lb;
}

// =====================================================================
// Tensor-core GEMM via mma.sync (3-term split), pre-split bf16 operands.
// R14-exact. MODE 0: fp32 out. MODE 1: split bf16 out (scaled).
// =====================================================================
#define TCB_AH 0
#define TCB_AL 16384
#define TCB_WH 32768
#define TCB_WL 49152
#define TC_SMEM 65536

template<int MODE>
__global__ void __launch_bounds__(256) tc_gemm_kernel(
    const __nv_bfloat16* __restrict__ Ah, const __nv_bfloat16* __restrict__ Al,
    const __nv_bfloat16* __restrict__ Wh, const __nv_bfloat16* __restrict__ Wl,
    const float* __restrict__ bias, float* __restrict__ C,
    __nv_bfloat16* __restrict__ Ch, __nv_bfloat16* __restrict__ Cl, float scale)
{
    extern __shared__ __align__(1024) char tcsm[];
    const int tid = threadIdx.x;
    const int lane = tid & 31, wid = tid >> 5;
    const int wr = wid >> 1, wc = wid & 1;
    const int m0 = blockIdx.x * 128;
    const int n0 = blockIdx.y * 128;
    const uint32_t sb = smem_u32(tcsm);

    float acc[2][8][4];
    #pragma unroll
    for (int mt = 0; mt < 2; mt++)
        #pragma unroll
        for (int nt = 0; nt < 8; nt++)
            #pragma unroll
            for (int i = 0; i < 4; i++) acc[mt][nt][i] = 0.f;

    const int a_row  = lane & 15;
    const int a_colb = (lane >> 4) << 4;
    const int b_row  = ((lane >> 4) << 3) + (lane & 7);
    const int b_colb = ((lane >> 3) & 1) << 4;

    #pragma unroll 1
    for (int kc = 0; kc < 8; kc++) {
        #pragma unroll
        for (int it = 0; it < 8; it++) {
            int e = tid + it * 256;
            int row = e >> 4, kq = e & 15;
            int so = GSWZ(row * 128 + kq * 8);
            size_t go = (size_t)(m0 + row) * DM + kc * 64 + kq * 4;
            size_t gw = (size_t)(n0 + row) * DM + kc * 64 + kq * 4;
            *reinterpret_cast<ull*>(tcsm + TCB_AH + so) = *reinterpret_cast<const ull*>(&Ah[go]);
            *reinterpret_cast<ull*>(tcsm + TCB_AL + so) = *reinterpret_cast<const ull*>(&Al[go]);
            *reinterpret_cast<ull*>(tcsm + TCB_WH + so) = *reinterpret_cast<const ull*>(&Wh[gw]);
            *reinterpret_cast<ull*>(tcsm + TCB_WL + so) = *reinterpret_cast<const ull*>(&Wl[gw]);
        }
        __syncthreads();

        #pragma unroll
        for (int k16 = 0; k16 < 4; k16++) {
            const int kb = k16 * 32;
            uint32_t ah[2][4], al[2][4];
            #pragma unroll
            for (int mt = 0; mt < 2; mt++) {
                int ro = (wr * 32 + mt * 16 + a_row) * 128 + kb + a_colb;
                uint32_t ad = sb + GSWZ(ro);
                LDM_X4(ah[mt], ad + TCB_AH);
                LDM_X4(al[mt], ad + TCB_AL);
            }
            #pragma unroll
            for (int p = 0; p < 4; p++) {
                int ro = (wc * 64 + p * 16 + b_row) * 128 + kb + b_colb;
                uint32_t bd = sb + GSWZ(ro);
                uint32_t bh[4], bl[4];
                LDM_X4(bh, bd + TCB_WH);
                LDM_X4(bl, bd + TCB_WL);
                #pragma unroll
                for (int mt = 0; mt < 2; mt++) {
                    mma16816(acc[mt][2 * p],     ah[mt], bh[0], bh[1]);
                    mma16816(acc[mt][2 * p],     ah[mt], bl[0], bl[1]);
                    mma16816(acc[mt][2 * p],     al[mt], bh[0], bh[1]);
                    mma16816(acc[mt][2 * p + 1], ah[mt], bh[2], bh[3]);
                    mma16816(acc[mt][2 * p + 1], ah[mt], bl[2], bl[3]);
                    mma16816(acc[mt][2 * p + 1], al[mt], bh[2], bh[3]);
                }
            }
        }
        __syncthreads();
    }

    const int g = lane >> 2, t2 = (lane & 3) << 1;
    #pragma unroll
    for (int nt = 0; nt < 8; nt++) {
        int col = n0 + wc * 64 + nt * 8 + t2;
        float b0 = bias[col], b1 = bias[col + 1];
        #pragma unroll
        for (int mt = 0; mt < 2; mt++) {
            int row = m0 + wr * 32 + mt * 16 + g;
            float v00 = acc[mt][nt][0] + b0, v01 = acc[mt][nt][1] + b1;
            float v10 = acc[mt][nt][2] + b0, v11 = acc[mt][nt][3] + b1;
            if (MODE == 0) {
                *reinterpret_cast<float2*>(&C[(size_t)row * DM + col])       = make_float2(v00, v01);
                *reinterpret_cast<float2*>(&C[(size_t)(row + 8) * DM + col]) = make_float2(v10, v11);
            } else {
                v00 *= scale; v01 *= scale; v10 *= scale; v11 *= scale;
                uint32_t ph, pl;
                splitp(v00, v01, ph, pl);
                *reinterpret_cast<uint32_t*>(&Ch[(size_t)row * DM + col]) = ph;
                *reinterpret_cast<uint32_t*>(&Cl[(size_t)row * DM + col]) = pl;
                splitp(v10, v11, ph, pl);
                *reinterpret_cast<uint32_t*>(&Ch[(size_t)(row + 8) * DM + col]) = ph;
                *reinterpret_cast<uint32_t*>(&Cl[(size_t)(row + 8) * DM + col]) = pl;
            }
        }
    }
}

// =====================================================================
// Tensor-core flash attention, split-KV, cp.async DOUBLE-BUFFERED K/V.
// CTA 128q, 64-key chunks, 8 warps 16q x 64k.
// Smem: Q (hi/lo) + 2 x {KH,KL,VH,VL} buffers. 110,592 B -> 2 CTA/SM.
// =====================================================================
#define AQH 0
#define AQL (AQH + 128 * 144)
#define QB  (AQL + 128 * 144)            // buffer region start (36864)
#define TARR (64 * 144)                  // one array: 9216 B
#define BUFSZ (4 * TARR)                 // 36864 B per buffer
#define KHO 0
#define KLO TARR
#define VHO (2 * TARR)
#define VLO (3 * TARR)
#define ATTN_SMEM (QB + 2 * BUFSZ)       // 110592 B

__global__ void __launch_bounds__(256, 2) attn_kernel(
    const __nv_bfloat16* __restrict__ Qh, const __nv_bfloat16* __restrict__ Ql,
    const __nv_bfloat16* __restrict__ Kh, const __nv_bfloat16* __restrict__ Kl,
    const __nv_bfloat16* __restrict__ Vh, const __nv_bfloat16* __restrict__ Vl)
{
    extern __shared__ __align__(1024) char smc[];
    const int tid = threadIdx.x;
    const int lane = tid & 31, wid = tid >> 5;
    const int bh = blockIdx.y;
    const int b = bh >> 3, h = bh & 7;
    const int q0 = blockIdx.x * 128;
    const int split = blockIdx.z;
    const int kbase = split * KPS;
    const uint32_t sb = smem_u32(smc);

    const size_t boff = (size_t)b * S_LEN * DM + (size_t)h * DH;
    const __nv_bfloat16* Qhb = Qh + boff;
    const __nv_bfloat16* Qlb = Ql + boff;
    const __nv_bfloat16* Khb = Kh + boff;
    const __nv_bfloat16* Klb = Kl + boff;
    const __nv_bfloat16* Vhb = Vh + boff;
    const __nv_bfloat16* Vlb = Vl + boff;

    // per-thread cp.async chunk coords: two 16B chunks per array
    const int c0 = tid, c1 = tid + 256;                 // 0..511
    const int r0c = c0 >> 3, d80 = (c0 & 7) << 3;       // key row, bf16 col
    const int r1c = c1 >> 3, d81 = (c1 & 7) << 3;

    // ---- stage Q (pure copy) ----
    #pragma unroll
    for (int it = 0; it < 8; it++) {
        int e = tid + it * 256;
        int d4 = (e & 15) << 2, qq = e >> 4;
        size_t go = (size_t)(q0 + qq) * DM + d4;
        *reinterpret_cast<ull*>(smc + AQH + qq * 144 + d4 * 2) =
            *reinterpret_cast<const ull*>(&Qhb[go]);
        *reinterpret_cast<ull*>(smc + AQL + qq * 144 + d4 * 2) =
            *reinterpret_cast<const ull*>(&Qlb[go]);
    }

    // ---- prologue: cp.async tile 0 into buffer 0 ----
    {
        const int kk0 = kbase;
        uint32_t dst = sb + QB;
        CP_ASYNC16(dst + KHO + r0c * 144 + d80 * 2, &Khb[(size_t)(kk0 + r0c) * DM + d80]);
        CP_ASYNC16(dst + KHO + r1c * 144 + d81 * 2, &Khb[(size_t)(kk0 + r1c) * DM + d81]);
        CP_ASYNC16(dst + KLO + r0c * 144 + d80 * 2, &Klb[(size_t)(kk0 + r0c) * DM + d80]);
        CP_ASYNC16(dst + KLO + r1c * 144 + d81 * 2, &Klb[(size_t)(kk0 + r1c) * DM + d81]);
        CP_ASYNC16(dst + VHO + r0c * 144 + d80 * 2, &Vhb[(size_t)(kk0 + r0c) * DM + d80]);
        CP_ASYNC16(dst + VHO + r1c * 144 + d81 * 2, &Vhb[(size_t)(kk0 + r1c) * DM + d81]);
        CP_ASYNC16(dst + VLO + r0c * 144 + d80 * 2, &Vlb[(size_t)(kk0 + r0c) * DM + d80]);
        CP_ASYNC16(dst + VLO + r1c * 144 + d81 * 2, &Vlb[(size_t)(kk0 + r1c) * DM + d81]);
        CP_COMMIT();
    }

    float oacc[8][4];
    #pragma unroll
    for (int j = 0; j < 8; j++)
        #pragma unroll
        for (int i = 0; i < 4; i++) oacc[j][i] = 0.f;
    float lrow0 = 0.f, lrow1 = 0.f;

    const int a_row  = lane & 15;
    const int a_colb = (lane >> 4) << 4;
    const int kb_row  = ((lane >> 4) << 3) + (lane & 7);   // K (non-trans B)
    const int kb_colb = ((lane >> 3) & 1) << 4;
    const int vb_row  = lane & 15;                          // V (trans B)
    const int vb_colb = (lane >> 4) << 4;

    CP_WAIT0();
    __syncthreads();

    #pragma unroll 1
    for (int kt = 0; kt < KPS / 64; kt++) {
        const uint32_t bb = sb + QB + (kt & 1) * BUFSZ;
        const bool more = (kt + 1 < KPS / 64);

        // ---- issue cp.async for next tile into the other buffer ----
        if (more) {
            const int kk1 = kbase + (kt + 1) * 64;
            uint32_t dst = sb + QB + ((kt + 1) & 1) * BUFSZ;
            CP_ASYNC16(dst + KHO + r0c * 144 + d80 * 2, &Khb[(size_t)(kk1 + r0c) * DM + d80]);
            CP_ASYNC16(dst + KHO + r1c * 144 + d81 * 2, &Khb[(size_t)(kk1 + r1c) * DM + d81]);
            CP_ASYNC16(dst + KLO + r0c * 144 + d80 * 2, &Klb[(size_t)(kk1 + r0c) * DM + d80]);
            CP_ASYNC16(dst + KLO + r1c * 144 + d81 * 2, &Klb[(size_t)(kk1 + r1c) * DM + d81]);
            CP_ASYNC16(dst + VHO + r0c * 144 + d80 * 2, &Vhb[(size_t)(kk1 + r0c) * DM + d80]);
            CP_ASYNC16(dst + VHO + r1c * 144 + d81 * 2, &Vhb[(size_t)(kk1 + r1c) * DM + d81]);
            CP_ASYNC16(dst + VLO + r0c * 144 + d80 * 2, &Vlb[(size_t)(kk1 + r0c) * DM + d80]);
            CP_ASYNC16(dst + VLO + r1c * 144 + d81 * 2, &Vlb[(size_t)(kk1 + r1c) * DM + d81]);
            CP_COMMIT();
        }

        // ---- S = Q @ K^T (3-term split) : 16q x 64k per warp ----
        float sacc[8][4];
        #pragma unroll
        for (int j = 0; j < 8; j++)
            #pragma unroll
            for (int i = 0; i < 4; i++) sacc[j][i] = 0.f;

        #pragma unroll
        for (int k16 = 0; k16 < 4; k16++) {
            uint32_t qa = sb + (wid * 16 + a_row) * 144 + k16 * 32 + a_colb;
            uint32_t ah[4], al[4];
            LDM_X4(ah, qa + AQH);
            LDM_X4(al, qa + AQL);
            #pragma unroll
            for (int p = 0; p < 4; p++) {
                uint32_t ka = bb + (p * 16 + kb_row) * 144 + k16 * 32 + kb_colb;
                uint32_t bh[4], bl[4];
                LDM_X4(bh, ka + KHO);
                LDM_X4(bl, ka + KLO);
                mma16816(sacc[2 * p],     ah, bh[0], bh[1]);
                mma16816(sacc[2 * p],     ah, bl[0], bl[1]);
                mma16816(sacc[2 * p],     al, bh[0], bh[1]);
                mma16816(sacc[2 * p + 1], ah, bh[2], bh[3]);
                mma16816(sacc[2 * p + 1], ah, bl[2], bl[3]);
                mma16816(sacc[2 * p + 1], al, bh[2], bh[3]);
            }
        }

        // ---- P = exp(S) in place; accumulate l ----
        #pragma unroll
        for (int j = 0; j < 8; j++) {
            sacc[j][0] = __expf(sacc[j][0]);
            sacc[j][1] = __expf(sacc[j][1]);
            sacc[j][2] = __expf(sacc[j][2]);
            sacc[j][3] = __expf(sacc[j][3]);
            lrow0 += sacc[j][0] + sacc[j][1];
            lrow1 += sacc[j][2] + sacc[j][3];
        }

        // ---- O += P @ V (P split 2, V split 2; 3 terms) ----
        #pragma unroll
        for (int kq = 0; kq < 4; kq++) {
            const float* t0 = sacc[2 * kq];
            const float* t1 = sacc[2 * kq + 1];
            uint32_t pah[4], pal[4];
            splitp(t0[0], t0[1], pah[0], pal[0]);
            splitp(t0[2], t0[3], pah[1], pal[1]);
            splitp(t1[0], t1[1], pah[2], pal[2]);
            splitp(t1[2], t1[3], pah[3], pal[3]);
            #pragma unroll
            for (int p = 0; p < 4; p++) {
                uint32_t va = bb + (kq * 16 + vb_row) * 144 + p * 32 + vb_colb;
                uint32_t vh[4], vl[4];
                LDM_X4_T(vh, va + VHO);
                LDM_X4_T(vl, va + VLO);
                mma16816(oacc[2 * p],     pah, vh[0], vh[1]);
                mma16816(oacc[2 * p],     pah, vl[0], vl[1]);
                mma16816(oacc[2 * p],     pal, vh[0], vh[1]);
                mma16816(oacc[2 * p + 1], pah, vh[2], vh[3]);
                mma16816(oacc[2 * p + 1], pah, vl[2], vl[3]);
                mma16816(oacc[2 * p + 1], pal, vh[2], vh[3]);
            }
        }

        if (more) CP_WAIT0();
        __syncthreads();   // publish next buffer; guard reuse of this one
    }

    // ---- epilogue ----
    const int g = lane >> 2, t4 = lane & 3;
    #pragma unroll
    for (int off = 1; off < 4; off <<= 1) {
        lrow0 += __shfl_xor_sync(0xffffffffu, lrow0, off);
        lrow1 += __shfl_xor_sync(0xffffffffu, lrow1, off);
    }

    float* Ob = g_opart + ((((size_t)split * B_SZ + b) * HN + h) * S_LEN + q0) * DH;
    const int r0 = wid * 16 + g, r1 = r0 + 8;
    #pragma unroll
    for (int j = 0; j < 8; j++) {
        int col = j * 8 + t4 * 2;
        *reinterpret_cast<float2*>(&Ob[(size_t)r0 * DH + col]) = make_float2(oacc[j][0], oacc[j][1]);
        *reinterpret_cast<float2*>(&Ob[(size_t)r1 * DH + col]) = make_float2(oacc[j][2], oacc[j][3]);
    }
    if (t4 == 0) {
        float* Lb = g_l + ((size_t)(split * B_SZ + b) * HN + h) * S_LEN + q0;
        Lb[r0] = lrow0;
        Lb[r1] = lrow1;
    }
}

// =====================================================================
// Merge split-KV partials -> pre-split bf16 context (h/l).
// =====================================================================
__global__ void __launch_bounds__(256) merge_kernel()
{
    int idx = blockIdx.x * 256 + threadIdx.x;
    int dv4 = (idx & 15) << 2;
    int q   = (idx >> 4) & 4095;
    int h   = (idx >> 16) & 7;
    int b   = idx >> 19;

    float sx = 0.f, sy = 0.f, sz = 0.f, sw = 0.f, lsum = 0.f;
    #pragma unroll
    for (int s = 0; s < NSPLIT; s++) {
        size_t ob = ((((size_t)s * B_SZ + b) * HN + h) * S_LEN + q) * DH + dv4;
        float4 v = *reinterpret_cast<const float4*>(&g_opart[ob]);
        sx += v.x; sy += v.y; sz += v.z; sw += v.w;
        lsum += g_l[((size_t)(s * B_SZ + b) * HN + h) * S_LEN + q];
    }
    float inv = 1.0f / lsum;
    uint32_t h0, l0, h1, l1;
    splitp(sx * inv, sy * inv, h0, l0);
    splitp(sz * inv, sw * inv, h1, l1);
    size_t co = ((size_t)b * S_LEN + q) * DM + h * DH + dv4;
    *reinterpret_cast<ull*>(&g_ctxh[co]) = (ull)h0 | ((ull)h1 << 32);
    *reinterpret_cast<ull*>(&g_ctxl[co]) = (ull)l0 | ((ull)l1 << 32);
}

// =====================================================================
extern "C" void kernel_launch(void* const* d_in, const int* in_sizes, int n_in,
                              void* d_out, int out_size)
{
    const float* q  = (const float*)d_in[0];
    const float* k  = (const float*)d_in[1];
    const float* v  = (const float*)d_in[2];
    const float* Wq = (const float*)d_in[3];
    const float* bq = (const float*)d_in[4];
    const float* Wk = (const float*)d_in[5];
    const float* bk = (const float*)d_in[6];
    const float* Wv = (const float*)d_in[7];
    const float* bv = (const float*)d_in[8];
    const float* Wo = (const float*)d_in[9];
    const float* bo = (const float*)d_in[10];
    float* out = (float*)d_out;

    __nv_bfloat16 *inh[3], *inl[3], *wh[4], *wl[4];
    __nv_bfloat16 *gqh, *gql, *gkh, *gkl, *gvh, *gvl, *gctxh, *gctxl;
    {
        __nv_bfloat16 *p;
        cudaGetSymbolAddress((void**)&p, g_inh);
        inh[0] = p; inh[1] = p + BSD; inh[2] = p + 2 * BSD;
        cudaGetSymbolAddress((void**)&p, g_inl);
        inl[0] = p; inl[1] = p + BSD; inl[2] = p + 2 * BSD;
        cudaGetSymbolAddress((void**)&p, g_wh);
        wh[0] = p; wh[1] = p + DM * DM; wh[2] = p + 2 * DM * DM; wh[3] = p + 3 * DM * DM;
        cudaGetSymbolAddress((void**)&p, g_wl);
        wl[0] = p; wl[1] = p + DM * DM; wl[2] = p + 2 * DM * DM; wl[3] = p + 3 * DM * DM;
    }
    cudaGetSymbolAddress((void**)&gqh, g_qh);
    cudaGetSymbolAddress((void**)&gql, g_ql);
    cudaGetSymbolAddress((void**)&gkh, g_kh);
    cudaGetSymbolAddress((void**)&gkl, g_kl);
    cudaGetSymbolAddress((void**)&gvh, g_vh);
    cudaGetSymbolAddress((void**)&gvl, g_vl);
    cudaGetSymbolAddress((void**)&gctxh, g_ctxh);
    cudaGetSymbolAddress((void**)&gctxl, g_ctxl);

    cudaFuncSetAttribute(attn_kernel, cudaFuncAttributeMaxDynamicSharedMemorySize, ATTN_SMEM);
    cudaFuncSetAttribute(tc_gemm_kernel<0>, cudaFuncAttributeMaxDynamicSharedMemorySize, TC_SMEM);
    cudaFuncSetAttribute(tc_gemm_kernel<1>, cudaFuncAttributeMaxDynamicSharedMemorySize, TC_SMEM);

    // ---- presplit inputs and weights ----
    const int IN4 = (int)(BSD / 4);          // 1048576
    const int W4  = DM * DM / 4;             // 65536
    presplit_kernel<<<IN4 / 256, 256>>>(q, inh[0], inl[0], IN4);
    presplit_kernel<<<IN4 / 256, 256>>>(k, inh[1], inl[1], IN4);
    presplit_kernel<<<IN4 / 256, 256>>>(v, inh[2], inl[2], IN4);
    presplit_kernel<<<W4 / 256, 256>>>(Wq, wh[0], wl[0], W4);
    presplit_kernel<<<W4 / 256, 256>>>(Wk, wh[1], wl[1], W4);
    presplit_kernel<<<W4 / 256, 256>>>(Wv, wh[2], wl[2], W4);
    presplit_kernel<<<W4 / 256, 256>>>(Wo, wh[3], wl[3], W4);

    // ---- projections (split bf16 out; Q pre-scaled by 1/8) ----
    dim3 ggrid(64, 4);
    tc_gemm_kernel<1><<<ggrid, 256, TC_SMEM>>>(inh[0], inl[0], wh[0], wl[0], bq, nullptr, gqh, gql, 0.125f);
    tc_gemm_kernel<1><<<ggrid, 256, TC_SMEM>>>(inh[1], inl[1], wh[1], wl[1], bk, nullptr, gkh, gkl, 1.0f);
    tc_gemm_kernel<1><<<ggrid, 256, TC_SMEM>>>(inh[2], inl[2], wh[2], wl[2], bv, nullptr, gvh, gvl, 1.0f);

    dim3 agrid(S_LEN / 128, B_SZ * HN, NSPLIT);   // (32, 16, 4)
    attn_kernel<<<agrid, 256, ATTN_SMEM>>>(gqh, gql, gkh, gkl, gvh, gvl);

    merge_kernel<<<(B_SZ * HN * S_LEN * (DH / 4)) / 256, 256>>>();   // 8192 blocks

    // ---- output projection (fp32 out) ----
    tc_gemm_kernel<0><<<ggrid, 256, TC_SMEM>>>(gctxh, gctxl, wh[3], wl[3], bo, out, nullptr, nullptr, 1.0f);
}

// round 17
// speedup vs baseline: 2.8495x; 1.0387x over previous
#include <cuda_runtime.h>
#include <cuda_bf16.h>
#include <cstdint>

#define S_LEN 4096
#define B_SZ  2
#define DM    512
#define HN    8
#define DH    64
#define NSPLIT 4
#define KPS   (S_LEN / NSPLIT)   // 1024 keys per split
#define BSD   ((size_t)B_SZ * S_LEN * DM)

typedef unsigned long long ull;

// ---------------- mma.sync helpers (baseline PTX, works under compute_103) ----
__device__ __forceinline__ uint32_t smem_u32(const void* p) {
    uint32_t a;
    asm("{ .reg .u64 t; cvta.to.shared.u64 t, %1; cvt.u32.u64 %0, t; }" : "=r"(a) : "l"(p));
    return a;
}
#define LDM_X4(r, addr)                                                        \
    asm volatile("ldmatrix.sync.aligned.m8n8.x4.shared.b16 {%0,%1,%2,%3}, [%4];" \
        : "=r"((r)[0]), "=r"((r)[1]), "=r"((r)[2]), "=r"((r)[3]) : "r"(addr))
#define LDM_X4_T(r, addr)                                                      \
    asm volatile("ldmatrix.sync.aligned.m8n8.x4.trans.shared.b16 {%0,%1,%2,%3}, [%4];" \
        : "=r"((r)[0]), "=r"((r)[1]), "=r"((r)[2]), "=r"((r)[3]) : "r"(addr))
#define CP_ASYNC16(dst, src)                                                   \
    asm volatile("cp.async.cg.shared.global [%0], [%1], 16;" :: "r"(dst), "l"(src))
#define CP_COMMIT()  asm volatile("cp.async.commit_group;" ::: "memory")
#define CP_WAIT0()   asm volatile("cp.async.wait_group 0;" ::: "memory")

__device__ __forceinline__ void mma16816(float* d, const uint32_t* a, uint32_t b0, uint32_t b1) {
    asm volatile(
        "mma.sync.aligned.m16n8k16.row.col.f32.bf16.bf16.f32 "
        "{%0,%1,%2,%3}, {%4,%5,%6,%7}, {%8,%9}, {%0,%1,%2,%3};"
        : "+f"(d[0]), "+f"(d[1]), "+f"(d[2]), "+f"(d[3])
        : "r"(a[0]), "r"(a[1]), "r"(a[2]), "r"(a[3]), "r"(b0), "r"(b1));
}
// pack {lo, hi} floats to bf16x2 (lo in bits 15:0)
__device__ __forceinline__ uint32_t cvt2(float hi, float lo) {
    uint32_t r; asm("cvt.rn.bf16x2.f32 %0, %1, %2;" : "=r"(r) : "f"(hi), "f"(lo)); return r;
}
// split pair (d0,d1) into hi bf16x2 + residual-lo bf16x2
__device__ __forceinline__ void splitp(float d0, float d1, uint32_t& ph, uint32_t& pl) {
    ph = cvt2(d1, d0);
    float h0 = __uint_as_float(ph << 16);
    float h1 = __uint_as_float(ph & 0xffff0000u);
    pl = cvt2(d1 - h1, d0 - h0);
}
// split a float4 into hi/lo bf16 quads (packed as 4x16-bit in a ull)
__device__ __forceinline__ void split4(float4 a, ull& hb, ull& lb) {
    uint32_t h0, l0, h1, l1;
    splitp(a.x, a.y, h0, l0);
    splitp(a.z, a.w, h1, l1);
    hb = (ull)h0 | ((ull)h1 << 32);
    lb = (ull)l0 | ((ull)l1 << 32);
}

// ---------------- scratch (no cudaMalloc allowed) ----------------
__device__ __nv_bfloat16 g_inh[3][BSD];
__device__ __nv_bfloat16 g_inl[3][BSD];
__device__ __nv_bfloat16 g_wh[4][DM * DM];
__device__ __nv_bfloat16 g_wl[4][DM * DM];
__device__ __nv_bfloat16 g_qh[BSD];
__device__ __nv_bfloat16 g_ql[BSD];
__device__ __nv_bfloat16 g_kh[BSD];
__device__ __nv_bfloat16 g_kl[BSD];
__device__ __nv_bfloat16 g_vh[BSD];
__device__ __nv_bfloat16 g_vl[BSD];
__device__ __nv_bfloat16 g_ctxh[BSD];
__device__ __nv_bfloat16 g_ctxl[BSD];
__device__ float g_opart[(size_t)NSPLIT * BSD];   // unnormalized per-split O
__device__ float g_l[NSPLIT * B_SZ * HN * S_LEN]; // per-split softmax denominators

// =====================================================================
// presplit (batched): fp32 -> (hi, lo) bf16. grid.z selects the array.
// =====================================================================
__global__ void __launch_bounds__(256) presplit3_kernel(
    const float* s0, const float* s1, const float* s2,
    __nv_bfloat16* h0p, __nv_bfloat16* l0p,
    __nv_bfloat16* h1p, __nv_bfloat16* l1p,
    __nv_bfloat16* h2p, __nv_bfloat16* l2p, int n4)
{
    int i = blockIdx.x * 256 + threadIdx.x;
    if (i >= n4) return;
    int z = blockIdx.z;
    const float* src = (z == 0) ? s0 : (z == 1) ? s1 : s2;
    __nv_bfloat16* h = (z == 0) ? h0p : (z == 1) ? h1p : h2p;
    __nv_bfloat16* l = (z == 0) ? l0p : (z == 1) ? l1p : l2p;
    float4 v = *reinterpret_cast<const float4*>(src + (size_t)i * 4);
    ull hb, lb;
    split4(v, hb, lb);
    *reinterpret_cast<ull*>(&h[(size_t)i * 4]) = hb;
    *reinterpret_cast<ull*>(&l[(size_t)i * 4]) = lb;
}
__global__ void __launch_bounds__(256) presplit4_kernel(
    const float* s0, const float* s1, const float* s2, const float* s3,
    __nv_bfloat16* hbase, __nv_bfloat16* lbase, int n4)
{
    int i = blockIdx.x * 256 + threadIdx.x;
    if (i >= n4) return;
    int z = blockIdx.z;
    const float* src = (z == 0) ? s0 : (z == 1) ? s1 : (z == 2) ? s2 : s3;
    __nv_bfloat16* h = hbase + (size_t)z * DM * DM;
    __nv_bfloat16* l = lbase + (size_t)z * DM * DM;
    float4 v = *reinterpret_cast<const float4*>(src + (size_t)i * 4);
    ull hb, lb;
    split4(v, hb, lb);
    *reinterpret_cast<ull*>(&h[(size_t)i * 4]) = hb;
    *reinterpret_cast<ull*>(&l[(size_t)i * 4]) = lb;
}

// =====================================================================
// Tensor-core GEMM, 3-term split, cp.async DOUBLE-BUFFERED, BK=32.
// CTA 128m x 128n, 8 warps a 32m x 64n. 16 K-chunks of 32.
// Smem: 2 buffers x 4 arrays[128 rows x 80B] = 81920 B -> 2 CTA/SM.
// Row stride 80B (5 granules, odd) -> conflict-free ldmatrix phases.
// MODE 0: fp32 out. MODE 1: split bf16 out (scaled).
// =====================================================================
#define GROW 80
#define GARR (128 * GROW)          // 10240 B
#define GAH 0
#define GAL GARR
#define GWH (2 * GARR)
#define GWL (3 * GARR)
#define GBUF (4 * GARR)            // 40960 B per buffer
#define TC_SMEM (2 * GBUF)         // 81920 B

template<int MODE>
__global__ void __launch_bounds__(256) tc_gemm_kernel(
    const __nv_bfloat16* __restrict__ Ah, const __nv_bfloat16* __restrict__ Al,
    const __nv_bfloat16* __restrict__ Wh, const __nv_bfloat16* __restrict__ Wl,
    const float* __restrict__ bias, float* __restrict__ C,
    __nv_bfloat16* __restrict__ Ch, __nv_bfloat16* __restrict__ Cl, float scale)
{
    extern __shared__ __align__(1024) char tcsm[];
    const int tid = threadIdx.x;
    const int lane = tid & 31, wid = tid >> 5;
    const int wr = wid >> 1, wc = wid & 1;
    const int m0 = blockIdx.x * 128;
    const int n0 = blockIdx.y * 128;
    const uint32_t sb = smem_u32(tcsm);

    float acc[2][8][4];
    #pragma unroll
    for (int mt = 0; mt < 2; mt++)
        #pragma unroll
        for (int nt = 0; nt < 8; nt++)
            #pragma unroll
            for (int i = 0; i < 4; i++) acc[mt][nt][i] = 0.f;

    const int a_row  = lane & 15;
    const int a_colb = (lane >> 4) << 4;
    const int b_row  = ((lane >> 4) << 3) + (lane & 7);
    const int b_colb = ((lane >> 3) & 1) << 4;

    // staging coords: per array 512 x 16B chunks; this thread does chunks tid, tid+256
    const int r0c = tid >> 2,           k80 = (tid & 3) << 3;          // row, bf16 col
    const int r1c = (tid + 256) >> 2,   k81 = ((tid + 256) & 3) << 3;
    const int s0o = r0c * GROW + (k80 << 1);                            // smem byte offset
    const int s1o = r1c * GROW + (k81 << 1);

    // ---- prologue: stage chunk 0 into buffer 0 ----
    {
        uint32_t dst = sb;
        CP_ASYNC16(dst + GAH + s0o, &Ah[(size_t)(m0 + r0c) * DM + k80]);
        CP_ASYNC16(dst + GAH + s1o, &Ah[(size_t)(m0 + r1c) * DM + k81]);
        CP_ASYNC16(dst + GAL + s0o, &Al[(size_t)(m0 + r0c) * DM + k80]);
        CP_ASYNC16(dst + GAL + s1o, &Al[(size_t)(m0 + r1c) * DM + k81]);
        CP_ASYNC16(dst + GWH + s0o, &Wh[(size_t)(n0 + r0c) * DM + k80]);
        CP_ASYNC16(dst + GWH + s1o, &Wh[(size_t)(n0 + r1c) * DM + k81]);
        CP_ASYNC16(dst + GWL + s0o, &Wl[(size_t)(n0 + r0c) * DM + k80]);
        CP_ASYNC16(dst + GWL + s1o, &Wl[(size_t)(n0 + r1c) * DM + k81]);
        CP_COMMIT();
    }
    CP_WAIT0();
    __syncthreads();

    const int NCH = DM / 32;   // 16
    #pragma unroll 1
    for (int kc = 0; kc < NCH; kc++) {
        const uint32_t bb = sb + (kc & 1) * GBUF;
        const bool more = (kc + 1 < NCH);
        if (more) {
            const int kb2 = (kc + 1) * 32;
            uint32_t dst = sb + ((kc + 1) & 1) * GBUF;
            CP_ASYNC16(dst + GAH + s0o, &Ah[(size_t)(m0 + r0c) * DM + kb2 + k80]);
            CP_ASYNC16(dst + GAH + s1o, &Ah[(size_t)(m0 + r1c) * DM + kb2 + k81]);
            CP_ASYNC16(dst + GAL + s0o, &Al[(size_t)(m0 + r0c) * DM + kb2 + k80]);
            CP_ASYNC16(dst + GAL + s1o, &Al[(size_t)(m0 + r1c) * DM + kb2 + k81]);
            CP_ASYNC16(dst + GWH + s0o, &Wh[(size_t)(n0 + r0c) * DM + kb2 + k80]);
            CP_ASYNC16(dst + GWH + s1o, &Wh[(size_t)(n0 + r1c) * DM + kb2 + k81]);
            CP_ASYNC16(dst + GWL + s0o, &Wl[(size_t)(n0 + r0c) * DM + kb2 + k80]);
            CP_ASYNC16(dst + GWL + s1o, &Wl[(size_t)(n0 + r1c) * DM + kb2 + k81]);
            CP_COMMIT();
        }

        #pragma unroll
        for (int k16 = 0; k16 < 2; k16++) {
            const int kb = k16 * 32;   // byte offset of k16 within 64B row
            uint32_t ah[2][4], al[2][4];
            #pragma unroll
            for (int mt = 0; mt < 2; mt++) {
                uint32_t ad = bb + (wr * 32 + mt * 16 + a_row) * GROW + kb + a_colb;
                LDM_X4(ah[mt], ad + GAH);
                LDM_X4(al[mt], ad + GAL);
            }
            #pragma unroll
            for (int p = 0; p < 4; p++) {
                uint32_t bd = bb + (wc * 64 + p * 16 + b_row) * GROW + kb + b_colb;
                uint32_t bh[4], bl[4];
                LDM_X4(bh, bd + GWH);
                LDM_X4(bl, bd + GWL);
                #pragma unroll
                for (int mt = 0; mt < 2; mt++) {
                    mma16816(acc[mt][2 * p],     ah[mt], bh[0], bh[1]);
                    mma16816(acc[mt][2 * p],     ah[mt], bl[0], bl[1]);
                    mma16816(acc[mt][2 * p],     al[mt], bh[0], bh[1]);
                    mma16816(acc[mt][2 * p + 1], ah[mt], bh[2], bh[3]);
                    mma16816(acc[mt][2 * p + 1], ah[mt], bl[2], bl[3]);
                    mma16816(acc[mt][2 * p + 1], al[mt], bh[2], bh[3]);
                }
            }
        }

        if (more) CP_WAIT0();
        __syncthreads();   // publish next buffer; guard reuse of this one
    }

    const int g = lane >> 2, t2 = (lane & 3) << 1;
    #pragma unroll
    for (int nt = 0; nt < 8; nt++) {
        int col = n0 + wc * 64 + nt * 8 + t2;
        float b0 = bias[col], b1 = bias[col + 1];
        #pragma unroll
        for (int mt = 0; mt < 2; mt++) {
            int row = m0 + wr * 32 + mt * 16 + g;
            float v00 = acc[mt][nt][0] + b0, v01 = acc[mt][nt][1] + b1;
            float v10 = acc[mt][nt][2] + b0, v11 = acc[mt][nt][3] + b1;
            if (MODE == 0) {
                *reinterpret_cast<float2*>(&C[(size_t)row * DM + col])       = make_float2(v00, v01);
                *reinterpret_cast<float2*>(&C[(size_t)(row + 8) * DM + col]) = make_float2(v10, v11);
            } else {
                v00 *= scale; v01 *= scale; v10 *= scale; v11 *= scale;
                uint32_t ph, pl;
                splitp(v00, v01, ph, pl);
                *reinterpret_cast<uint32_t*>(&Ch[(size_t)row * DM + col]) = ph;
                *reinterpret_cast<uint32_t*>(&Cl[(size_t)row * DM + col]) = pl;
                splitp(v10, v11, ph, pl);
                *reinterpret_cast<uint32_t*>(&Ch[(size_t)(row + 8) * DM + col]) = ph;
                *reinterpret_cast<uint32_t*>(&Cl[(size_t)(row + 8) * DM + col]) = pl;
            }
        }
    }
}

// =====================================================================
// Tensor-core flash attention, split-KV, cp.async double-buffered. R15-exact.
// =====================================================================
#define AQH 0
#define AQL (AQH + 128 * 144)
#define QB  (AQL + 128 * 144)            // buffer region start (36864)
#define TARR (64 * 144)                  // one array: 9216 B
#define BUFSZ (4 * TARR)                 // 36864 B per buffer
#define KHO 0
#define KLO TARR
#define VHO (2 * TARR)
#define VLO (3 * TARR)
#define ATTN_SMEM (QB + 2 * BUFSZ)       // 110592 B

__global__ void __launch_bounds__(256, 2) attn_kernel(
    const __nv_bfloat16* __restrict__ Qh, const __nv_bfloat16* __restrict__ Ql,
    const __nv_bfloat16* __restrict__ Kh, const __nv_bfloat16* __restrict__ Kl,
    const __nv_bfloat16* __restrict__ Vh, const __nv_bfloat16* __restrict__ Vl)
{
    extern __shared__ __align__(1024) char smc[];
    const int tid = threadIdx.x;
    const int lane = tid & 31, wid = tid >> 5;
    const int bh = blockIdx.y;
    const int b = bh >> 3, h = bh & 7;
    const int q0 = blockIdx.x * 128;
    const int split = blockIdx.z;
    const int kbase = split * KPS;
    const uint32_t sb = smem_u32(smc);

    const size_t boff = (size_t)b * S_LEN * DM + (size_t)h * DH;
    const __nv_bfloat16* Qhb = Qh + boff;
    const __nv_bfloat16* Qlb = Ql + boff;
    const __nv_bfloat16* Khb = Kh + boff;
    const __nv_bfloat16* Klb = Kl + boff;
    const __nv_bfloat16* Vhb = Vh + boff;
    const __nv_bfloat16* Vlb = Vl + boff;

    const int c0 = tid, c1 = tid + 256;
    const int r0c = c0 >> 3, d80 = (c0 & 7) << 3;
    const int r1c = c1 >> 3, d81 = (c1 & 7) << 3;

    // ---- stage Q (pure copy) ----
    #pragma unroll
    for (int it = 0; it < 8; it++) {
        int e = tid + it * 256;
        int d4 = (e & 15) << 2, qq = e >> 4;
        size_t go = (size_t)(q0 + qq) * DM + d4;
        *reinterpret_cast<ull*>(smc + AQH + qq * 144 + d4 * 2) =
            *reinterpret_cast<const ull*>(&Qhb[go]);
        *reinterpret_cast<ull*>(smc + AQL + qq * 144 + d4 * 2) =
            *reinterpret_cast<const ull*>(&Qlb[go]);
    }

    // ---- prologue: cp.async tile 0 into buffer 0 ----
    {
        const int kk0 = kbase;
        uint32_t dst = sb + QB;
        CP_ASYNC16(dst + KHO + r0c * 144 + d80 * 2, &Khb[(size_t)(kk0 + r0c) * DM + d80]);
        CP_ASYNC16(dst + KHO + r1c * 144 + d81 * 2, &Khb[(size_t)(kk0 + r1c) * DM + d81]);
        CP_ASYNC16(dst + KLO + r0c * 144 + d80 * 2, &Klb[(size_t)(kk0 + r0c) * DM + d80]);
        CP_ASYNC16(dst + KLO + r1c * 144 + d81 * 2, &Klb[(size_t)(kk0 + r1c) * DM + d81]);
        CP_ASYNC16(dst + VHO + r0c * 144 + d80 * 2, &Vhb[(size_t)(kk0 + r0c) * DM + d80]);
        CP_ASYNC16(dst + VHO + r1c * 144 + d81 * 2, &Vhb[(size_t)(kk0 + r1c) * DM + d81]);
        CP_ASYNC16(dst + VLO + r0c * 144 + d80 * 2, &Vlb[(size_t)(kk0 + r0c) * DM + d80]);
        CP_ASYNC16(dst + VLO + r1c * 144 + d81 * 2, &Vlb[(size_t)(kk0 + r1c) * DM + d81]);
        CP_COMMIT();
    }

    float oacc[8][4];
    #pragma unroll
    for (int j = 0; j < 8; j++)
        #pragma unroll
        for (int i = 0; i < 4; i++) oacc[j][i] = 0.f;
    float lrow0 = 0.f, lrow1 = 0.f;

    const int a_row  = lane & 15;
    const int a_colb = (lane >> 4) << 4;
    const int kb_row  = ((lane >> 4) << 3) + (lane & 7);
    const int kb_colb = ((lane >> 3) & 1) << 4;
    const int vb_row  = lane & 15;
    const int vb_colb = (lane >> 4) << 4;

    CP_WAIT0();
    __syncthreads();

    #pragma unroll 1
    for (int kt = 0; kt < KPS / 64; kt++) {
        const uint32_t bb = sb + QB + (kt & 1) * BUFSZ;
        const bool more = (kt + 1 < KPS / 64);

        if (more) {
            const int kk1 = kbase + (kt + 1) * 64;
            uint32_t dst = sb + QB + ((kt + 1) & 1) * BUFSZ;
            CP_ASYNC16(dst + KHO + r0c * 144 + d80 * 2, &Khb[(size_t)(kk1 + r0c) * DM + d80]);
            CP_ASYNC16(dst + KHO + r1c * 144 + d81 * 2, &Khb[(size_t)(kk1 + r1c) * DM + d81]);
            CP_ASYNC16(dst + KLO + r0c * 144 + d80 * 2, &Klb[(size_t)(kk1 + r0c) * DM + d80]);
            CP_ASYNC16(dst + KLO + r1c * 144 + d81 * 2, &Klb[(size_t)(kk1 + r1c) * DM + d81]);
            CP_ASYNC16(dst + VHO + r0c * 144 + d80 * 2, &Vhb[(size_t)(kk1 + r0c) * DM + d80]);
            CP_ASYNC16(dst + VHO + r1c * 144 + d81 * 2, &Vhb[(size_t)(kk1 + r1c) * DM + d81]);
            CP_ASYNC16(dst + VLO + r0c * 144 + d80 * 2, &Vlb[(size_t)(kk1 + r0c) * DM + d80]);
            CP_ASYNC16(dst + VLO + r1c * 144 + d81 * 2, &Vlb[(size_t)(kk1 + r1c) * DM + d81]);
            CP_COMMIT();
        }

        // ---- S = Q @ K^T (3-term split) ----
        float sacc[8][4];
        #pragma unroll
        for (int j = 0; j < 8; j++)
            #pragma unroll
            for (int i = 0; i < 4; i++) sacc[j][i] = 0.f;

        #pragma unroll
        for (int k16 = 0; k16 < 4; k16++) {
            uint32_t qa = sb + (wid * 16 + a_row) * 144 + k16 * 32 + a_colb;
            uint32_t ah[4], al[4];
            LDM_X4(ah, qa + AQH);
            LDM_X4(al, qa + AQL);
            #pragma unroll
            for (int p = 0; p < 4; p++) {
                uint32_t ka = bb + (p * 16 + kb_row) * 144 + k16 * 32 + kb_colb;
                uint32_t bh[4], bl[4];
                LDM_X4(bh, ka + KHO);
                LDM_X4(bl, ka + KLO);
                mma16816(sacc[2 * p],     ah, bh[0], bh[1]);
                mma16816(sacc[2 * p],     ah, bl[0], bl[1]);
                mma16816(sacc[2 * p],     al, bh[0], bh[1]);
                mma16816(sacc[2 * p + 1], ah, bh[2], bh[3]);
                mma16816(sacc[2 * p + 1], ah, bl[2], bl[3]);
                mma16816(sacc[2 * p + 1], al, bh[2], bh[3]);
            }
        }

        // ---- P = exp(S); accumulate l ----
        #pragma unroll
        for (int j = 0; j < 8; j++) {
            sacc[j][0] = __expf(sacc[j][0]);
            sacc[j][1] = __expf(sacc[j][1]);
            sacc[j][2] = __expf(sacc[j][2]);
            sacc[j][3] = __expf(sacc[j][3]);
            lrow0 += sacc[j][0] + sacc[j][1];
            lrow1 += sacc[j][2] + sacc[j][3];
        }

        // ---- O += P @ V ----
        #pragma unroll
        for (int kq = 0; kq < 4; kq++) {
            const float* t0 = sacc[2 * kq];
            const float* t1 = sacc[2 * kq + 1];
            uint32_t pah[4], pal[4];
            splitp(t0[0], t0[1], pah[0], pal[0]);
            splitp(t0[2], t0[3], pah[1], pal[1]);
            splitp(t1[0], t1[1], pah[2], pal[2]);
            splitp(t1[2], t1[3], pah[3], pal[3]);
            #pragma unroll
            for (int p = 0; p < 4; p++) {
                uint32_t va = bb + (kq * 16 + vb_row) * 144 + p * 32 + vb_colb;
                uint32_t vh[4], vl[4];
                LDM_X4_T(vh, va + VHO);
                LDM_X4_T(vl, va + VLO);
                mma16816(oacc[2 * p],     pah, vh[0], vh[1]);
                mma16816(oacc[2 * p],     pah, vl[0], vl[1]);
                mma16816(oacc[2 * p],     pal, vh[0], vh[1]);
                mma16816(oacc[2 * p + 1], pah, vh[2], vh[3]);
                mma16816(oacc[2 * p + 1], pah, vl[2], vl[3]);
                mma16816(oacc[2 * p + 1], pal, vh[2], vh[3]);
            }
        }

        if (more) CP_WAIT0();
        __syncthreads();
    }

    // ---- epilogue ----
    const int g = lane >> 2, t4 = lane & 3;
    #pragma unroll
    for (int off = 1; off < 4; off <<= 1) {
        lrow0 += __shfl_xor_sync(0xffffffffu, lrow0, off);
        lrow1 += __shfl_xor_sync(0xffffffffu, lrow1, off);
    }

    float* Ob = g_opart + ((((size_t)split * B_SZ + b) * HN + h) * S_LEN + q0) * DH;
    const int r0 = wid * 16 + g, r1 = r0 + 8;
    #pragma unroll
    for (int j = 0; j < 8; j++) {
        int col = j * 8 + t4 * 2;
        *reinterpret_cast<float2*>(&Ob[(size_t)r0 * DH + col]) = make_float2(oacc[j][0], oacc[j][1]);
        *reinterpret_cast<float2*>(&Ob[(size_t)r1 * DH + col]) = make_float2(oacc[j][2], oacc[j][3]);
    }
    if (t4 == 0) {
        float* Lb = g_l + ((size_t)(split * B_SZ + b) * HN + h) * S_LEN + q0;
        Lb[r0] = lrow0;
        Lb[r1] = lrow1;
    }
}

// =====================================================================
// Merge split-KV partials -> pre-split bf16 context (h/l).
// =====================================================================
__global__ void __launch_bounds__(256) merge_kernel()
{
    int idx = blockIdx.x * 256 + threadIdx.x;
    int dv4 = (idx & 15) << 2;
    int q   = (idx >> 4) & 4095;
    int h   = (idx >> 16) & 7;
    int b   = idx >> 19;

    float sx = 0.f, sy = 0.f, sz = 0.f, sw = 0.f, lsum = 0.f;
    #pragma unroll
    for (int s = 0; s < NSPLIT; s++) {
        size_t ob = ((((size_t)s * B_SZ + b) * HN + h) * S_LEN + q) * DH + dv4;
        float4 v = *reinterpret_cast<const float4*>(&g_opart[ob]);
        sx += v.x; sy += v.y; sz += v.z; sw += v.w;
        lsum += g_l[((size_t)(s * B_SZ + b) * HN + h) * S_LEN + q];
    }
    float inv = 1.0f / lsum;
    uint32_t h0, l0, h1, l1;
    splitp(sx * inv, sy * inv, h0, l0);
    splitp(sz * inv, sw * inv, h1, l1);
    size_t co = ((size_t)b * S_LEN + q) * DM + h * DH + dv4;
    *reinterpret_cast<ull*>(&g_ctxh[co]) = (ull)h0 | ((ull)h1 << 32);
    *reinterpret_cast<ull*>(&g_ctxl[co]) = (ull)l0 | ((ull)l1 << 32);
}

// =====================================================================
extern "C" void kernel_launch(void* const* d_in, const int* in_sizes, int n_in,
                              void* d_out, int out_size)
{
    const float* q  = (const float*)d_in[0];
    const float* k  = (const float*)d_in[1];
    const float* v  = (const float*)d_in[2];
    const float* Wq = (const float*)d_in[3];
    const float* bq = (const float*)d_in[4];
    const float* Wk = (const float*)d_in[5];
    const float* bk = (const float*)d_in[6];
    const float* Wv = (const float*)d_in[7];
    const float* bv = (const float*)d_in[8];
    const float* Wo = (const float*)d_in[9];
    const float* bo = (const float*)d_in[10];
    float* out = (float*)d_out;

    __nv_bfloat16 *inh[3], *inl[3], *whb, *wlb;
    __nv_bfloat16 *gqh, *gql, *gkh, *gkl, *gvh, *gvl, *gctxh, *gctxl;
    {
        __nv_bfloat16 *p;
        cudaGetSymbolAddress((void**)&p, g_inh);
        inh[0] = p; inh[1] = p + BSD; inh[2] = p + 2 * BSD;
        cudaGetSymbolAddress((void**)&p, g_inl);
        inl[0] = p; inl[1] = p + BSD; inl[2] = p + 2 * BSD;
        cudaGetSymbolAddress((void**)&whb, g_wh);
        cudaGetSymbolAddress((void**)&wlb, g_wl);
    }
    cudaGetSymbolAddress((void**)&gqh, g_qh);
    cudaGetSymbolAddress((void**)&gql, g_ql);
    cudaGetSymbolAddress((void**)&gkh, g_kh);
    cudaGetSymbolAddress((void**)&gkl, g_kl);
    cudaGetSymbolAddress((void**)&gvh, g_vh);
    cudaGetSymbolAddress((void**)&gvl, g_vl);
    cudaGetSymbolAddress((void**)&gctxh, g_ctxh);
    cudaGetSymbolAddress((void**)&gctxl, g_ctxl);

    cudaFuncSetAttribute(attn_kernel, cudaFuncAttributeMaxDynamicSharedMemorySize, ATTN_SMEM);
    cudaFuncSetAttribute(tc_gemm_kernel<0>, cudaFuncAttributeMaxDynamicSharedMemorySize, TC_SMEM);
    cudaFuncSetAttribute(tc_gemm_kernel<1>, cudaFuncAttributeMaxDynamicSharedMemorySize, TC_SMEM);

    // ---- presplit inputs (batched) and weights (batched) ----
    const int IN4 = (int)(BSD / 4);          // 1048576
    const int W4  = DM * DM / 4;             // 65536
    dim3 pin(IN4 / 256, 1, 3);
    presplit3_kernel<<<pin, 256>>>(q, k, v, inh[0], inl[0], inh[1], inl[1], inh[2], inl[2], IN4);
    dim3 pw(W4 / 256, 1, 4);
    presplit4_kernel<<<pw, 256>>>(Wq, Wk, Wv, Wo, whb, wlb, W4);

    // ---- projections (split bf16 out; Q pre-scaled by 1/8) ----
    dim3 ggrid(64, 4);
    tc_gemm_kernel<1><<<ggrid, 256, TC_SMEM>>>(inh[0], inl[0], whb + 0 * DM * DM, wlb + 0 * DM * DM, bq, nullptr, gqh, gql, 0.125f);
    tc_gemm_kernel<1><<<ggrid, 256, TC_SMEM>>>(inh[1], inl[1], whb + 1 * DM * DM, wlb + 1 * DM * DM, bk, nullptr, gkh, gkl, 1.0f);
    tc_gemm_kernel<1><<<ggrid, 256, TC_SMEM>>>(inh[2], inl[2], whb + 2 * DM * DM, wlb + 2 * DM * DM, bv, nullptr, gvh, gvl, 1.0f);

    dim3 agrid(S_LEN / 128, B_SZ * HN, NSPLIT);   // (32, 16, 4)
    attn_kernel<<<agrid, 256, ATTN_SMEM>>>(gqh, gql, gkh, gkl, gvh, gvl);

    merge_kernel<<<(B_SZ * HN * S_LEN * (DH / 4)) / 256, 256>>>();   // 8192 blocks

    // ---- output projection (fp32 out) ----
    tc_gemm_kernel<0><<<ggrid, 256, TC_SMEM>>>(gctxh, gctxl, whb + 3 * DM * DM, wlb + 3 * DM * DM, bo, out, nullptr, nullptr, 1.0f);
}